// round 1
// baseline (speedup 1.0000x reference)
#include <cuda_runtime.h>
#include <math.h>

#define EMB   768
#define HEADS 12
#define TT    2048
#define BB    4
#define C3    (3 * EMB)
#define DH    64

// ---------------- scratch (device globals: allocation-free) ----------------
__device__ float g_qkv[(size_t)BB * TT * C3];   // [B*T, 3C]  = 75.5 MB
__device__ float g_y  [(size_t)BB * TT * EMB];  // [B*T, C]   = 25 MB

// ============================================================================
// SGEMM: C[M,N] = A[M,K] @ B[K,N] + bias[N]
// 128x128 tile, BK=8, 256 threads, 8x8 register tile per thread.
// Requires M%128==0, N%128==0, K%8==0 (true for all shapes here).
// ============================================================================
__global__ __launch_bounds__(256) void sgemm_bias_kernel(
    const float* __restrict__ A, const float* __restrict__ B,
    const float* __restrict__ bias, float* __restrict__ C,
    int M, int N, int K)
{
    __shared__ float As[8][128];   // transposed A tile
    __shared__ float Bs[8][128];

    const int tid = threadIdx.x;
    const int bm  = blockIdx.y * 128;
    const int bn  = blockIdx.x * 128;

    const int a_r = tid >> 1;             // 0..127
    const int a_k = (tid & 1) << 2;       // 0 or 4
    const int b_k = tid >> 5;             // 0..7
    const int b_c = (tid & 31) << 2;      // 0..124

    const int row0 = (tid >> 4) << 3;     // 0..120
    const int col0 = (tid & 15) << 3;     // 0..120

    float acc[8][8];
    #pragma unroll
    for (int i = 0; i < 8; i++)
        #pragma unroll
        for (int j = 0; j < 8; j++) acc[i][j] = 0.f;

    const float* Ag = A + (size_t)(bm + a_r) * K + a_k;
    const float* Bg = B + (size_t)b_k * N + bn + b_c;

    for (int k0 = 0; k0 < K; k0 += 8) {
        float4 av = *(const float4*)(Ag + k0);
        float4 bv = *(const float4*)(Bg + (size_t)k0 * N);
        __syncthreads();
        As[a_k + 0][a_r] = av.x;
        As[a_k + 1][a_r] = av.y;
        As[a_k + 2][a_r] = av.z;
        As[a_k + 3][a_r] = av.w;
        *(float4*)&Bs[b_k][b_c] = bv;
        __syncthreads();

        #pragma unroll
        for (int kk = 0; kk < 8; kk++) {
            float af[8], bf[8];
            *(float4*)&af[0] = *(const float4*)&As[kk][row0];
            *(float4*)&af[4] = *(const float4*)&As[kk][row0 + 4];
            *(float4*)&bf[0] = *(const float4*)&Bs[kk][col0];
            *(float4*)&bf[4] = *(const float4*)&Bs[kk][col0 + 4];
            #pragma unroll
            for (int i = 0; i < 8; i++)
                #pragma unroll
                for (int j = 0; j < 8; j++)
                    acc[i][j] += af[i] * bf[j];
        }
    }

    float bs[8];
    #pragma unroll
    for (int j = 0; j < 8; j++) bs[j] = bias[bn + col0 + j];

    #pragma unroll
    for (int i = 0; i < 8; i++) {
        float* cp = C + (size_t)(bm + row0 + i) * N + bn + col0;
        float4 o0, o1;
        o0.x = acc[i][0] + bs[0]; o0.y = acc[i][1] + bs[1];
        o0.z = acc[i][2] + bs[2]; o0.w = acc[i][3] + bs[3];
        o1.x = acc[i][4] + bs[4]; o1.y = acc[i][5] + bs[5];
        o1.z = acc[i][6] + bs[6]; o1.w = acc[i][7] + bs[7];
        *(float4*)cp       = o0;
        *(float4*)(cp + 4) = o1;
    }
}

// ============================================================================
// Causal flash attention (fp32).
// Grid: (T/64, B*H). Block: 256 threads (16x16), each owns a 4x4 S/O subtile.
// Online softmax in registers; P staged through smem for the PV GEMM.
// qkv layout: [B*T, 3C]; Q cols h*64, K cols 768+h*64, V cols 1536+h*64.
// ============================================================================
#define ASTR 68   // padded smem row stride (floats)

__global__ __launch_bounds__(256) void attn_kernel(
    const float* __restrict__ qkv, float* __restrict__ y)
{
    extern __shared__ float smn[];
    float* Qs = smn;                 // 64 x ASTR
    float* Ks = smn + 64 * ASTR;
    float* Vs = smn + 2 * 64 * ASTR;
    float* Ps = smn + 3 * 64 * ASTR;

    const int tid = threadIdx.x;
    const int tx  = tid & 15;
    const int ty  = tid >> 4;
    const int r0  = ty << 2;   // query sub-rows  (0..60)
    const int c0  = tx << 2;   // key / dim cols  (0..60)

    const int qtile = blockIdx.x;
    const int bh    = blockIdx.y;
    const int b     = bh / HEADS;
    const int h     = bh - b * HEADS;

    const float* base  = qkv + (size_t)b * TT * C3 + h * DH;
    const int    qbase = qtile * 64;

    // ---- load Q tile (64x64) ----
    {
        const int lr = tid >> 2;
        const int lc = (tid & 3) << 2;
        const float* gp = base + (size_t)(qbase + lr) * C3;
        #pragma unroll
        for (int u = 0; u < 4; u++) {
            int c = lc + u * 16;
            *(float4*)(Qs + lr * ASTR + c) = *(const float4*)(gp + c);
        }
    }

    float m_i[4], l_i[4], acc[4][4];
    #pragma unroll
    for (int i = 0; i < 4; i++) {
        m_i[i] = -INFINITY;
        l_i[i] = 0.f;
        #pragma unroll
        for (int j = 0; j < 4; j++) acc[i][j] = 0.f;
    }

    const float sm_scale = 0.125f;  // 1/sqrt(64)

    for (int kt = 0; kt <= qtile; kt++) {
        const int kbase = kt * 64;
        __syncthreads();   // previous PV done reading Vs/Ps; Qs visible on iter 0
        // ---- load K, V tiles ----
        {
            const int lr = tid >> 2;
            const int lc = (tid & 3) << 2;
            const float* gk = base + EMB     + (size_t)(kbase + lr) * C3;
            const float* gv = base + 2 * EMB + (size_t)(kbase + lr) * C3;
            #pragma unroll
            for (int u = 0; u < 4; u++) {
                int c = lc + u * 16;
                *(float4*)(Ks + lr * ASTR + c) = *(const float4*)(gk + c);
                *(float4*)(Vs + lr * ASTR + c) = *(const float4*)(gv + c);
            }
        }
        __syncthreads();

        // ---- S = Q @ K^T  (4x4 per thread) ----
        float s[4][4];
        #pragma unroll
        for (int i = 0; i < 4; i++)
            #pragma unroll
            for (int j = 0; j < 4; j++) s[i][j] = 0.f;

        #pragma unroll
        for (int k = 0; k < 64; k += 4) {
            float qf[4][4], kf[4][4];
            #pragma unroll
            for (int i = 0; i < 4; i++)
                *(float4*)qf[i] = *(const float4*)(Qs + (r0 + i) * ASTR + k);
            #pragma unroll
            for (int j = 0; j < 4; j++)
                *(float4*)kf[j] = *(const float4*)(Ks + (c0 + j) * ASTR + k);
            #pragma unroll
            for (int i = 0; i < 4; i++)
                #pragma unroll
                for (int j = 0; j < 4; j++)
                    #pragma unroll
                    for (int u = 0; u < 4; u++)
                        s[i][j] += qf[i][u] * kf[j][u];
        }

        // ---- scale + causal mask (diagonal tile only) ----
        if (kt == qtile) {
            #pragma unroll
            for (int i = 0; i < 4; i++)
                #pragma unroll
                for (int j = 0; j < 4; j++)
                    s[i][j] = (kbase + c0 + j <= qbase + r0 + i)
                              ? s[i][j] * sm_scale : -INFINITY;
        } else {
            #pragma unroll
            for (int i = 0; i < 4; i++)
                #pragma unroll
                for (int j = 0; j < 4; j++)
                    s[i][j] *= sm_scale;
        }

        // ---- online softmax (row reduce over 16 tx lanes) ----
        #pragma unroll
        for (int i = 0; i < 4; i++) {
            float mt = fmaxf(fmaxf(s[i][0], s[i][1]), fmaxf(s[i][2], s[i][3]));
            #pragma unroll
            for (int off = 1; off < 16; off <<= 1)
                mt = fmaxf(mt, __shfl_xor_sync(0xffffffffu, mt, off));
            float mn    = fmaxf(m_i[i], mt);
            float alpha = __expf(m_i[i] - mn);
            m_i[i] = mn;
            float rs = 0.f;
            #pragma unroll
            for (int j = 0; j < 4; j++) {
                float p = __expf(s[i][j] - mn);
                s[i][j] = p;
                rs += p;
            }
            #pragma unroll
            for (int off = 1; off < 16; off <<= 1)
                rs += __shfl_xor_sync(0xffffffffu, rs, off);
            l_i[i] = l_i[i] * alpha + rs;
            #pragma unroll
            for (int j = 0; j < 4; j++) acc[i][j] *= alpha;
        }

        // ---- stage P, then acc += P @ V ----
        #pragma unroll
        for (int i = 0; i < 4; i++)
            *(float4*)(Ps + (r0 + i) * ASTR + c0) =
                make_float4(s[i][0], s[i][1], s[i][2], s[i][3]);
        __syncthreads();

        #pragma unroll
        for (int k = 0; k < 64; k += 4) {
            float pf[4][4], vf[4][4];
            #pragma unroll
            for (int i = 0; i < 4; i++)
                *(float4*)pf[i] = *(const float4*)(Ps + (r0 + i) * ASTR + k);
            #pragma unroll
            for (int u = 0; u < 4; u++)
                *(float4*)vf[u] = *(const float4*)(Vs + (k + u) * ASTR + c0);
            #pragma unroll
            for (int i = 0; i < 4; i++)
                #pragma unroll
                for (int u = 0; u < 4; u++)
                    #pragma unroll
                    for (int j = 0; j < 4; j++)
                        acc[i][j] += pf[i][u] * vf[u][j];
        }
    }

    // ---- normalize + write y[b*T + q][h*64 + d] ----
    float* yp = y + ((size_t)b * TT + qbase) * EMB + h * DH;
    #pragma unroll
    for (int i = 0; i < 4; i++) {
        float inv = 1.f / l_i[i];
        float4 o = make_float4(acc[i][0] * inv, acc[i][1] * inv,
                               acc[i][2] * inv, acc[i][3] * inv);
        *(float4*)(yp + (size_t)(r0 + i) * EMB + c0) = o;
    }
}

// ============================================================================
// launch
// ============================================================================
extern "C" void kernel_launch(void* const* d_in, const int* in_sizes, int n_in,
                              void* d_out, int out_size)
{
    const float* x      = (const float*)d_in[0];
    const float* w_qkv  = (const float*)d_in[1];
    const float* b_qkv  = (const float*)d_in[2];
    const float* w_proj = (const float*)d_in[3];
    const float* b_proj = (const float*)d_in[4];
    float*       out    = (float*)d_out;

    void *pqkv = nullptr, *py = nullptr;
    cudaGetSymbolAddress(&pqkv, g_qkv);
    cudaGetSymbolAddress(&py,   g_y);

    const int ATTN_SMEM = 4 * 64 * ASTR * sizeof(float);  // 69632
    cudaFuncSetAttribute(attn_kernel,
                         cudaFuncAttributeMaxDynamicSharedMemorySize, ATTN_SMEM);

    const int M = BB * TT;  // 8192

    // 1) qkv = x @ w_qkv + b_qkv
    dim3 g1(C3 / 128, M / 128);     // (18, 64)
    sgemm_bias_kernel<<<g1, 256>>>(x, w_qkv, b_qkv, (float*)pqkv, M, C3, EMB);

    // 2) y = causal_attention(qkv)
    dim3 g2(TT / 64, BB * HEADS);   // (32, 48)
    attn_kernel<<<g2, 256, ATTN_SMEM>>>((const float*)pqkv, (float*)py);

    // 3) out = y @ w_proj + b_proj
    dim3 g3(EMB / 128, M / 128);    // (6, 64)
    sgemm_bias_kernel<<<g3, 256>>>((const float*)py, w_proj, b_proj, out, M, EMB, EMB);
}

// round 2
// speedup vs baseline: 1.0036x; 1.0036x over previous
#include <cuda_runtime.h>
#include <math.h>

#define EMB   768
#define HEADS 12
#define TT    2048
#define BB    4
#define C3    (3 * EMB)
#define DH    64

// ---------------- scratch (device globals: allocation-free) ----------------
__device__ float g_qkv[(size_t)BB * TT * C3];   // [B*T, 3C]  = 75.5 MB
__device__ float g_y  [(size_t)BB * TT * EMB];  // [B*T, C]   = 25 MB

// ============================================================================
// SGEMM: C[M,N] = A[M,K] @ B[K,N] + bias[N]
// 128x128 tile, BK=8, 256 threads, 8x8 register tile per thread.
// Requires M%128==0, N%128==0, K%8==0 (true for all shapes here).
// ============================================================================
__global__ __launch_bounds__(256) void sgemm_bias_kernel(
    const float* __restrict__ A, const float* __restrict__ B,
    const float* __restrict__ bias, float* __restrict__ C,
    int M, int N, int K)
{
    __shared__ float As[8][128];   // transposed A tile
    __shared__ float Bs[8][128];

    const int tid = threadIdx.x;
    const int bm  = blockIdx.y * 128;
    const int bn  = blockIdx.x * 128;

    const int a_r = tid >> 1;             // 0..127
    const int a_k = (tid & 1) << 2;       // 0 or 4
    const int b_k = tid >> 5;             // 0..7
    const int b_c = (tid & 31) << 2;      // 0..124

    const int row0 = (tid >> 4) << 3;     // 0..120
    const int col0 = (tid & 15) << 3;     // 0..120

    float acc[8][8];
    #pragma unroll
    for (int i = 0; i < 8; i++)
        #pragma unroll
        for (int j = 0; j < 8; j++) acc[i][j] = 0.f;

    const float* Ag = A + (size_t)(bm + a_r) * K + a_k;
    const float* Bg = B + (size_t)b_k * N + bn + b_c;

    for (int k0 = 0; k0 < K; k0 += 8) {
        float4 av = *(const float4*)(Ag + k0);
        float4 bv = *(const float4*)(Bg + (size_t)k0 * N);
        __syncthreads();
        As[a_k + 0][a_r] = av.x;
        As[a_k + 1][a_r] = av.y;
        As[a_k + 2][a_r] = av.z;
        As[a_k + 3][a_r] = av.w;
        *(float4*)&Bs[b_k][b_c] = bv;
        __syncthreads();

        #pragma unroll
        for (int kk = 0; kk < 8; kk++) {
            float af[8], bf[8];
            *(float4*)&af[0] = *(const float4*)&As[kk][row0];
            *(float4*)&af[4] = *(const float4*)&As[kk][row0 + 4];
            *(float4*)&bf[0] = *(const float4*)&Bs[kk][col0];
            *(float4*)&bf[4] = *(const float4*)&Bs[kk][col0 + 4];
            #pragma unroll
            for (int i = 0; i < 8; i++)
                #pragma unroll
                for (int j = 0; j < 8; j++)
                    acc[i][j] += af[i] * bf[j];
        }
    }

    float bs[8];
    #pragma unroll
    for (int j = 0; j < 8; j++) bs[j] = bias[bn + col0 + j];

    #pragma unroll
    for (int i = 0; i < 8; i++) {
        float* cp = C + (size_t)(bm + row0 + i) * N + bn + col0;
        float4 o0, o1;
        o0.x = acc[i][0] + bs[0]; o0.y = acc[i][1] + bs[1];
        o0.z = acc[i][2] + bs[2]; o0.w = acc[i][3] + bs[3];
        o1.x = acc[i][4] + bs[4]; o1.y = acc[i][5] + bs[5];
        o1.z = acc[i][6] + bs[6]; o1.w = acc[i][7] + bs[7];
        *(float4*)cp       = o0;
        *(float4*)(cp + 4) = o1;
    }
}

// ============================================================================
// Causal flash attention (fp32).
// Grid: (T/64, B*H). Block: 256 threads (16x16), each owns a 4x4 S/O subtile.
// Online softmax in registers; P staged through smem for the PV GEMM.
// qkv layout: [B*T, 3C]; Q cols h*64, K cols 768+h*64, V cols 1536+h*64.
// ============================================================================
#define ASTR 68   // padded smem row stride (floats)

__global__ __launch_bounds__(256) void attn_kernel(
    const float* __restrict__ qkv, float* __restrict__ y)
{
    extern __shared__ float smn[];
    float* Qs = smn;                 // 64 x ASTR
    float* Ks = smn + 64 * ASTR;
    float* Vs = smn + 2 * 64 * ASTR;
    float* Ps = smn + 3 * 64 * ASTR;

    const int tid = threadIdx.x;
    const int tx  = tid & 15;
    const int ty  = tid >> 4;
    const int r0  = ty << 2;   // query sub-rows  (0..60)
    const int c0  = tx << 2;   // key / dim cols  (0..60)

    const int qtile = blockIdx.x;
    const int bh    = blockIdx.y;
    const int b     = bh / HEADS;
    const int h     = bh - b * HEADS;

    const float* base  = qkv + (size_t)b * TT * C3 + h * DH;
    const int    qbase = qtile * 64;

    // ---- load Q tile (64x64) ----
    {
        const int lr = tid >> 2;
        const int lc = (tid & 3) << 2;
        const float* gp = base + (size_t)(qbase + lr) * C3;
        #pragma unroll
        for (int u = 0; u < 4; u++) {
            int c = lc + u * 16;
            *(float4*)(Qs + lr * ASTR + c) = *(const float4*)(gp + c);
        }
    }

    float m_i[4], l_i[4], acc[4][4];
    #pragma unroll
    for (int i = 0; i < 4; i++) {
        m_i[i] = -INFINITY;
        l_i[i] = 0.f;
        #pragma unroll
        for (int j = 0; j < 4; j++) acc[i][j] = 0.f;
    }

    const float sm_scale = 0.125f;  // 1/sqrt(64)

    for (int kt = 0; kt <= qtile; kt++) {
        const int kbase = kt * 64;
        __syncthreads();   // previous PV done reading Vs/Ps; Qs visible on iter 0
        // ---- load K, V tiles ----
        {
            const int lr = tid >> 2;
            const int lc = (tid & 3) << 2;
            const float* gk = base + EMB     + (size_t)(kbase + lr) * C3;
            const float* gv = base + 2 * EMB + (size_t)(kbase + lr) * C3;
            #pragma unroll
            for (int u = 0; u < 4; u++) {
                int c = lc + u * 16;
                *(float4*)(Ks + lr * ASTR + c) = *(const float4*)(gk + c);
                *(float4*)(Vs + lr * ASTR + c) = *(const float4*)(gv + c);
            }
        }
        __syncthreads();

        // ---- S = Q @ K^T  (4x4 per thread) ----
        float s[4][4];
        #pragma unroll
        for (int i = 0; i < 4; i++)
            #pragma unroll
            for (int j = 0; j < 4; j++) s[i][j] = 0.f;

        #pragma unroll
        for (int k = 0; k < 64; k += 4) {
            float qf[4][4], kf[4][4];
            #pragma unroll
            for (int i = 0; i < 4; i++)
                *(float4*)qf[i] = *(const float4*)(Qs + (r0 + i) * ASTR + k);
            #pragma unroll
            for (int j = 0; j < 4; j++)
                *(float4*)kf[j] = *(const float4*)(Ks + (c0 + j) * ASTR + k);
            #pragma unroll
            for (int i = 0; i < 4; i++)
                #pragma unroll
                for (int j = 0; j < 4; j++)
                    #pragma unroll
                    for (int u = 0; u < 4; u++)
                        s[i][j] += qf[i][u] * kf[j][u];
        }

        // ---- scale + causal mask (diagonal tile only) ----
        if (kt == qtile) {
            #pragma unroll
            for (int i = 0; i < 4; i++)
                #pragma unroll
                for (int j = 0; j < 4; j++)
                    s[i][j] = (kbase + c0 + j <= qbase + r0 + i)
                              ? s[i][j] * sm_scale : -INFINITY;
        } else {
            #pragma unroll
            for (int i = 0; i < 4; i++)
                #pragma unroll
                for (int j = 0; j < 4; j++)
                    s[i][j] *= sm_scale;
        }

        // ---- online softmax (row reduce over 16 tx lanes) ----
        #pragma unroll
        for (int i = 0; i < 4; i++) {
            float mt = fmaxf(fmaxf(s[i][0], s[i][1]), fmaxf(s[i][2], s[i][3]));
            #pragma unroll
            for (int off = 1; off < 16; off <<= 1)
                mt = fmaxf(mt, __shfl_xor_sync(0xffffffffu, mt, off));
            float mn    = fmaxf(m_i[i], mt);
            float alpha = __expf(m_i[i] - mn);
            m_i[i] = mn;
            float rs = 0.f;
            #pragma unroll
            for (int j = 0; j < 4; j++) {
                float p = __expf(s[i][j] - mn);
                s[i][j] = p;
                rs += p;
            }
            #pragma unroll
            for (int off = 1; off < 16; off <<= 1)
                rs += __shfl_xor_sync(0xffffffffu, rs, off);
            l_i[i] = l_i[i] * alpha + rs;
            #pragma unroll
            for (int j = 0; j < 4; j++) acc[i][j] *= alpha;
        }

        // ---- stage P, then acc += P @ V ----
        #pragma unroll
        for (int i = 0; i < 4; i++)
            *(float4*)(Ps + (r0 + i) * ASTR + c0) =
                make_float4(s[i][0], s[i][1], s[i][2], s[i][3]);
        __syncthreads();

        #pragma unroll
        for (int k = 0; k < 64; k += 4) {
            float pf[4][4], vf[4][4];
            #pragma unroll
            for (int i = 0; i < 4; i++)
                *(float4*)pf[i] = *(const float4*)(Ps + (r0 + i) * ASTR + k);
            #pragma unroll
            for (int u = 0; u < 4; u++)
                *(float4*)vf[u] = *(const float4*)(Vs + (k + u) * ASTR + c0);
            #pragma unroll
            for (int i = 0; i < 4; i++)
                #pragma unroll
                for (int u = 0; u < 4; u++)
                    #pragma unroll
                    for (int j = 0; j < 4; j++)
                        acc[i][j] += pf[i][u] * vf[u][j];
        }
    }

    // ---- normalize + write y[b*T + q][h*64 + d] ----
    float* yp = y + ((size_t)b * TT + qbase) * EMB + h * DH;
    #pragma unroll
    for (int i = 0; i < 4; i++) {
        float inv = 1.f / l_i[i];
        float4 o = make_float4(acc[i][0] * inv, acc[i][1] * inv,
                               acc[i][2] * inv, acc[i][3] * inv);
        *(float4*)(yp + (size_t)(r0 + i) * EMB + c0) = o;
    }
}

// ============================================================================
// launch
// ============================================================================
extern "C" void kernel_launch(void* const* d_in, const int* in_sizes, int n_in,
                              void* d_out, int out_size)
{
    const float* x      = (const float*)d_in[0];
    const float* w_qkv  = (const float*)d_in[1];
    const float* b_qkv  = (const float*)d_in[2];
    const float* w_proj = (const float*)d_in[3];
    const float* b_proj = (const float*)d_in[4];
    float*       out    = (float*)d_out;

    void *pqkv = nullptr, *py = nullptr;
    cudaGetSymbolAddress(&pqkv, g_qkv);
    cudaGetSymbolAddress(&py,   g_y);

    const int ATTN_SMEM = 4 * 64 * ASTR * sizeof(float);  // 69632
    cudaFuncSetAttribute(attn_kernel,
                         cudaFuncAttributeMaxDynamicSharedMemorySize, ATTN_SMEM);

    const int M = BB * TT;  // 8192

    // 1) qkv = x @ w_qkv + b_qkv
    dim3 g1(C3 / 128, M / 128);     // (18, 64)
    sgemm_bias_kernel<<<g1, 256>>>(x, w_qkv, b_qkv, (float*)pqkv, M, C3, EMB);

    // 2) y = causal_attention(qkv)
    dim3 g2(TT / 64, BB * HEADS);   // (32, 48)
    attn_kernel<<<g2, 256, ATTN_SMEM>>>((const float*)pqkv, (float*)py);

    // 3) out = y @ w_proj + b_proj
    dim3 g3(EMB / 128, M / 128);    // (6, 64)
    sgemm_bias_kernel<<<g3, 256>>>((const float*)py, w_proj, b_proj, out, M, EMB, EMB);
}

// round 3
// speedup vs baseline: 2.7057x; 2.6961x over previous
#include <cuda_runtime.h>
#include <cuda_bf16.h>
#include <math.h>

#define EMB 768
#define HEADS 12
#define TT 2048
#define BB 4
#define C3 (3*EMB)
#define MM (BB*TT)
typedef __nv_bfloat16 bf;

// ------------- scratch (device globals, allocation-free) -------------
__device__ __align__(16) bf g_xh[MM*EMB],  g_xl[MM*EMB];
__device__ __align__(16) bf g_wqh[C3*EMB], g_wql[C3*EMB];   // w_qkv^T [N][K]
__device__ __align__(16) bf g_wph[EMB*EMB],g_wpl[EMB*EMB];  // w_proj^T
__device__ __align__(16) bf g_qh[(size_t)MM*C3], g_ql[(size_t)MM*C3];
__device__ __align__(16) bf g_yh[MM*EMB],  g_yl[MM*EMB];

// ------------- helpers -------------
__device__ __forceinline__ void split2(float x, float y, unsigned &hi, unsigned &lo){
    __nv_bfloat16 a=__float2bfloat16(x), b=__float2bfloat16(y);
    hi=(unsigned)__bfloat16_as_ushort(a)|((unsigned)__bfloat16_as_ushort(b)<<16);
    __nv_bfloat16 c=__float2bfloat16(x-__bfloat162float(a));
    __nv_bfloat16 d=__float2bfloat16(y-__bfloat162float(b));
    lo=(unsigned)__bfloat16_as_ushort(c)|((unsigned)__bfloat16_as_ushort(d)<<16);
}
#define MMA(D,A,B) asm volatile("mma.sync.aligned.m16n8k16.row.col.f32.bf16.bf16.f32 " \
  "{%0,%1,%2,%3},{%4,%5,%6,%7},{%8,%9},{%0,%1,%2,%3};" \
  : "+f"(D[0]),"+f"(D[1]),"+f"(D[2]),"+f"(D[3]) \
  : "r"(A[0]),"r"(A[1]),"r"(A[2]),"r"(A[3]),"r"(B[0]),"r"(B[1]))
__device__ __forceinline__ void ldsm4(unsigned a, unsigned r[4]){
    asm volatile("ldmatrix.sync.aligned.m8n8.x4.shared.b16 {%0,%1,%2,%3},[%4];"
      :"=r"(r[0]),"=r"(r[1]),"=r"(r[2]),"=r"(r[3]):"r"(a));
}
__device__ __forceinline__ void ldsm4t(unsigned a, unsigned r[4]){
    asm volatile("ldmatrix.sync.aligned.m8n8.x4.trans.shared.b16 {%0,%1,%2,%3},[%4];"
      :"=r"(r[0]),"=r"(r[1]),"=r"(r[2]),"=r"(r[3]):"r"(a));
}
#define CPA(d,s) asm volatile("cp.async.cg.shared.global [%0],[%1],16;"::"r"(d),"l"(s))

// ------------- conversion kernels -------------
__global__ void vsplit(const float* __restrict__ x, bf* hi, bf* lo, int n){
    int i=(blockIdx.x*blockDim.x+threadIdx.x)*2;
    if(i<n){ unsigned h,l; split2(x[i],x[i+1],h,l);
        *(unsigned*)(hi+i)=h; *(unsigned*)(lo+i)=l; }
}
__global__ void tsplit(const float* __restrict__ w, bf* th, bf* tl, int R, int C){
    __shared__ float t[32][33];
    int c0=blockIdx.x*32, r0=blockIdx.y*32, tx=threadIdx.x, ty=threadIdx.y;
    #pragma unroll
    for(int i=0;i<32;i+=8) t[ty+i][tx]=w[(size_t)(r0+ty+i)*C+c0+tx];
    __syncthreads();
    #pragma unroll
    for(int i=0;i<32;i+=8){
        float v=t[tx][ty+i];
        bf hv=__float2bfloat16(v);
        th[(size_t)(c0+ty+i)*R+r0+tx]=hv;
        tl[(size_t)(c0+ty+i)*R+r0+tx]=__float2bfloat16(v-__bfloat162float(hv));
    }
}

// ------------- GEMM: C[M,N] = (Ah+Al)[M,K] @ (Bh+Bl)[N,K]^T + bias -------------
#define SASTR 40
#define TILEBF (128*SASTR)
template<int SPLITOUT>
__global__ __launch_bounds__(256,1) void gemm_mma(
    const bf* __restrict__ Ah, const bf* __restrict__ Al,
    const bf* __restrict__ Bh, const bf* __restrict__ Bl,
    const float* __restrict__ bias,
    float* __restrict__ Cf, bf* __restrict__ Ch, bf* __restrict__ Cl,
    int M, int N, int K)
{
    extern __shared__ bf sm[];
    const int tid=threadIdx.x, lane=tid&31, w=tid>>5;
    const int wm=(w>>2)*64, wn=(w&3)*32;
    const int bm=blockIdx.y*128, bn=blockIdx.x*128;
    unsigned sb0=(unsigned)__cvta_generic_to_shared(sm);
    float acc[4][4][4];
    #pragma unroll
    for(int a=0;a<4;a++)
      #pragma unroll
      for(int b=0;b<4;b++){acc[a][b][0]=0;acc[a][b][1]=0;acc[a][b][2]=0;acc[a][b][3]=0;}

    auto loadstage=[&](int st,int k0){
        unsigned base=sb0+st*(4*TILEBF*2);
        const bf* gA[2]={Ah,Al}; const bf* gB[2]={Bh,Bl};
        #pragma unroll
        for(int h=0;h<2;h++){
            #pragma unroll
            for(int i=0;i<2;i++){
                int c=tid+i*256, r=c>>2, kc=(c&3)*8;
                CPA(base+h*TILEBF*2+(r*SASTR+kc)*2, gA[h]+(size_t)(bm+r)*K+k0+kc);
                CPA(base+(2+h)*TILEBF*2+(r*SASTR+kc)*2, gB[h]+(size_t)(bn+r)*K+k0+kc);
            }
        }
        asm volatile("cp.async.commit_group;");
    };

    const int NIT=K/32;
    loadstage(0,0);
    for(int it=0;it<NIT;it++){
        if(it+1<NIT){ loadstage((it+1)&1,(it+1)*32);
            asm volatile("cp.async.wait_group 1;"); }
        else asm volatile("cp.async.wait_group 0;");
        __syncthreads();
        unsigned sb=sb0+(it&1)*(4*TILEBF*2);
        #pragma unroll
        for(int ks=0;ks<2;ks++){
            unsigned ah[4][4], al[4][4];
            int kb=ks*16+(lane>>4)*8;
            #pragma unroll
            for(int mf=0;mf<4;mf++){
                int row=wm+mf*16+(lane&15);
                ldsm4(sb+(row*SASTR+kb)*2, ah[mf]);
                ldsm4(sb+TILEBF*2+(row*SASTR+kb)*2, al[mf]);
            }
            #pragma unroll
            for(int nb=0;nb<2;nb++){
                unsigned bh[4], bl[4];
                int row=wn+nb*16+(lane&15);
                ldsm4(sb+2*TILEBF*2+(row*SASTR+kb)*2, bh);
                ldsm4(sb+3*TILEBF*2+(row*SASTR+kb)*2, bl);
                unsigned b0h[2]={bh[0],bh[2]}, b1h[2]={bh[1],bh[3]};
                unsigned b0l[2]={bl[0],bl[2]}, b1l[2]={bl[1],bl[3]};
                #pragma unroll
                for(int mf=0;mf<4;mf++){
                    MMA(acc[mf][2*nb],ah[mf],b0h); MMA(acc[mf][2*nb],ah[mf],b0l);
                    MMA(acc[mf][2*nb],al[mf],b0h);
                    MMA(acc[mf][2*nb+1],ah[mf],b1h); MMA(acc[mf][2*nb+1],ah[mf],b1l);
                    MMA(acc[mf][2*nb+1],al[mf],b1h);
                }
            }
        }
        __syncthreads();
    }
    int g=lane>>2, tg=(lane&3)*2;
    #pragma unroll
    for(int mf=0;mf<4;mf++){
        int r0=bm+wm+mf*16+g;
        #pragma unroll
        for(int nf=0;nf<4;nf++){
            int col=bn+wn+nf*8+tg;
            float b0=bias[col], b1=bias[col+1];
            float v0=acc[mf][nf][0]+b0, v1=acc[mf][nf][1]+b1;
            float v2=acc[mf][nf][2]+b0, v3=acc[mf][nf][3]+b1;
            if(SPLITOUT){
                unsigned hi,lo;
                split2(v0,v1,hi,lo);
                *(unsigned*)(Ch+(size_t)r0*N+col)=hi; *(unsigned*)(Cl+(size_t)r0*N+col)=lo;
                split2(v2,v3,hi,lo);
                *(unsigned*)(Ch+(size_t)(r0+8)*N+col)=hi; *(unsigned*)(Cl+(size_t)(r0+8)*N+col)=lo;
            }else{
                *(float2*)(Cf+(size_t)r0*N+col)=make_float2(v0,v1);
                *(float2*)(Cf+(size_t)(r0+8)*N+col)=make_float2(v2,v3);
            }
        }
    }
}

// ------------- causal flash attention, bf16 split mma -------------
#define QSTR 72
__global__ __launch_bounds__(256,1) void attn_mma(
    const bf* __restrict__ qh, const bf* __restrict__ ql,
    bf* __restrict__ yh, bf* __restrict__ yl)
{
    extern __shared__ bf sm[];
    const int QH=0, QL=128*QSTR, KH=2*128*QSTR, KL=KH+64*QSTR,
              VH=KL+64*QSTR, VL=VH+64*QSTR;
    const int tid=threadIdx.x, lane=tid&31, w=tid>>5;
    const int qt=gridDim.x-1-blockIdx.x, qb=qt*128;
    const int bh_=blockIdx.y, b=bh_/HEADS, h=bh_-b*HEADS;
    const size_t rowbase=(size_t)b*TT*C3+h*64;
    unsigned sb=(unsigned)__cvta_generic_to_shared(sm);

    #pragma unroll
    for(int i=0;i<4;i++){
        int c=tid+i*256, r=c>>3, kc=(c&7)*8;
        *(uint4*)(sm+QH+r*QSTR+kc)=*(const uint4*)(qh+rowbase+(size_t)(qb+r)*C3+kc);
        *(uint4*)(sm+QL+r*QSTR+kc)=*(const uint4*)(ql+rowbase+(size_t)(qb+r)*C3+kc);
    }
    __syncthreads();
    unsigned qfh[4][4], qfl[4][4];
    {
        int row=w*16+(lane&15);
        #pragma unroll
        for(int ks=0;ks<4;ks++){
            int kb=ks*16+(lane>>4)*8;
            ldsm4(sb+(QH+row*QSTR+kb)*2, qfh[ks]);
            ldsm4(sb+(QL+row*QSTR+kb)*2, qfl[ks]);
        }
    }
    float m0=-1e30f,m1=-1e30f,l0=0.f,l1=0.f,o[8][4];
    #pragma unroll
    for(int i=0;i<8;i++){o[i][0]=0;o[i][1]=0;o[i][2]=0;o[i][3]=0;}
    const float SC=0.18033688f;  // 0.125 * log2(e)
    const int g=lane>>2, tg=(lane&3)*2;
    const int nkt=qb/64+2;

    for(int kt=0;kt<nkt;kt++){
        int kb=kt*64;
        __syncthreads();
        #pragma unroll
        for(int i=0;i<2;i++){
            int c=tid+i*256, r=c>>3, kc=(c&7)*8;
            size_t go=rowbase+(size_t)(kb+r)*C3+kc;
            *(uint4*)(sm+KH+r*QSTR+kc)=*(const uint4*)(qh+go+EMB);
            *(uint4*)(sm+KL+r*QSTR+kc)=*(const uint4*)(ql+go+EMB);
            *(uint4*)(sm+VH+r*QSTR+kc)=*(const uint4*)(qh+go+2*EMB);
            *(uint4*)(sm+VL+r*QSTR+kc)=*(const uint4*)(ql+go+2*EMB);
        }
        __syncthreads();
        float s[8][4];
        #pragma unroll
        for(int i=0;i<8;i++){s[i][0]=0;s[i][1]=0;s[i][2]=0;s[i][3]=0;}
        #pragma unroll
        for(int ks=0;ks<4;ks++){
            int kbb=ks*16+(lane>>4)*8;
            #pragma unroll
            for(int nb=0;nb<4;nb++){
                unsigned kh4[4],kl4[4];
                int row=nb*16+(lane&15);
                ldsm4(sb+(KH+row*QSTR+kbb)*2,kh4);
                ldsm4(sb+(KL+row*QSTR+kbb)*2,kl4);
                unsigned b0h[2]={kh4[0],kh4[2]}, b1h[2]={kh4[1],kh4[3]};
                unsigned b0l[2]={kl4[0],kl4[2]}, b1l[2]={kl4[1],kl4[3]};
                MMA(s[2*nb],qfh[ks],b0h); MMA(s[2*nb],qfh[ks],b0l); MMA(s[2*nb],qfl[ks],b0h);
                MMA(s[2*nb+1],qfh[ks],b1h); MMA(s[2*nb+1],qfh[ks],b1l); MMA(s[2*nb+1],qfl[ks],b1h);
            }
        }
        bool domask=(kb+63 > qb+w*16);
        #pragma unroll
        for(int nf=0;nf<8;nf++)
            #pragma unroll
            for(int r=0;r<4;r++){
                float v=s[nf][r]*SC;
                if(domask){
                    int key=kb+nf*8+tg+(r&1);
                    int qr=qb+w*16+g+((r>>1)<<3);
                    if(key>qr) v=-1e30f;
                }
                s[nf][r]=v;
            }
        float mx0=-1e30f,mx1=-1e30f;
        #pragma unroll
        for(int nf=0;nf<8;nf++){
            mx0=fmaxf(mx0,fmaxf(s[nf][0],s[nf][1]));
            mx1=fmaxf(mx1,fmaxf(s[nf][2],s[nf][3]));
        }
        mx0=fmaxf(mx0,__shfl_xor_sync(0xffffffffu,mx0,1));
        mx0=fmaxf(mx0,__shfl_xor_sync(0xffffffffu,mx0,2));
        mx1=fmaxf(mx1,__shfl_xor_sync(0xffffffffu,mx1,1));
        mx1=fmaxf(mx1,__shfl_xor_sync(0xffffffffu,mx1,2));
        float nm0=fmaxf(m0,mx0), nm1=fmaxf(m1,mx1);
        float a0=exp2f(m0-nm0), a1=exp2f(m1-nm1);
        m0=nm0; m1=nm1;
        float rs0=0.f, rs1=0.f;
        #pragma unroll
        for(int nf=0;nf<8;nf++){
            s[nf][0]=exp2f(s[nf][0]-nm0); s[nf][1]=exp2f(s[nf][1]-nm0);
            s[nf][2]=exp2f(s[nf][2]-nm1); s[nf][3]=exp2f(s[nf][3]-nm1);
            rs0+=s[nf][0]+s[nf][1]; rs1+=s[nf][2]+s[nf][3];
        }
        rs0+=__shfl_xor_sync(0xffffffffu,rs0,1); rs0+=__shfl_xor_sync(0xffffffffu,rs0,2);
        rs1+=__shfl_xor_sync(0xffffffffu,rs1,1); rs1+=__shfl_xor_sync(0xffffffffu,rs1,2);
        l0=l0*a0+rs0; l1=l1*a1+rs1;
        #pragma unroll
        for(int i=0;i<8;i++){o[i][0]*=a0;o[i][1]*=a0;o[i][2]*=a1;o[i][3]*=a1;}
        #pragma unroll
        for(int ks=0;ks<4;ks++){
            unsigned ph[4],pl[4];
            split2(s[2*ks][0],s[2*ks][1],ph[0],pl[0]);
            split2(s[2*ks][2],s[2*ks][3],ph[1],pl[1]);
            split2(s[2*ks+1][0],s[2*ks+1][1],ph[2],pl[2]);
            split2(s[2*ks+1][2],s[2*ks+1][3],ph[3],pl[3]);
            int row=ks*16+(lane&15);
            #pragma unroll
            for(int db=0;db<4;db++){
                unsigned vh4[4],vl4[4];
                int dbb=db*16+(lane>>4)*8;
                ldsm4t(sb+(VH+row*QSTR+dbb)*2,vh4);
                ldsm4t(sb+(VL+row*QSTR+dbb)*2,vl4);
                unsigned b0h[2]={vh4[0],vh4[1]}, b1h[2]={vh4[2],vh4[3]};
                unsigned b0l[2]={vl4[0],vl4[1]}, b1l[2]={vl4[2],vl4[3]};
                MMA(o[2*db],ph,b0h); MMA(o[2*db],ph,b0l); MMA(o[2*db],pl,b0h);
                MMA(o[2*db+1],ph,b1h); MMA(o[2*db+1],ph,b1l); MMA(o[2*db+1],pl,b1h);
            }
        }
    }
    float i0=1.f/l0, i1=1.f/l1;
    #pragma unroll
    for(int dn=0;dn<8;dn++){
        int col=h*64+dn*8+tg;
        size_t r0=(size_t)b*TT+qb+w*16+g;
        unsigned hi,lo;
        split2(o[dn][0]*i0,o[dn][1]*i0,hi,lo);
        *(unsigned*)(yh+r0*EMB+col)=hi; *(unsigned*)(yl+r0*EMB+col)=lo;
        split2(o[dn][2]*i1,o[dn][3]*i1,hi,lo);
        *(unsigned*)(yh+(r0+8)*EMB+col)=hi; *(unsigned*)(yl+(r0+8)*EMB+col)=lo;
    }
}

// ------------- launch -------------
extern "C" void kernel_launch(void* const* d_in, const int* in_sizes, int n_in,
                              void* d_out, int out_size)
{
    const float* x=(const float*)d_in[0];
    const float* w_qkv=(const float*)d_in[1];
    const float* b_qkv=(const float*)d_in[2];
    const float* w_proj=(const float*)d_in[3];
    const float* b_proj=(const float*)d_in[4];
    float* out=(float*)d_out;

    void *xh,*xl,*wqh,*wql,*wph,*wpl,*qhp,*qlp,*yhp,*ylp;
    cudaGetSymbolAddress(&xh,g_xh);   cudaGetSymbolAddress(&xl,g_xl);
    cudaGetSymbolAddress(&wqh,g_wqh); cudaGetSymbolAddress(&wql,g_wql);
    cudaGetSymbolAddress(&wph,g_wph); cudaGetSymbolAddress(&wpl,g_wpl);
    cudaGetSymbolAddress(&qhp,g_qh);  cudaGetSymbolAddress(&qlp,g_ql);
    cudaGetSymbolAddress(&yhp,g_yh);  cudaGetSymbolAddress(&ylp,g_yl);

    const int GSM=2*4*TILEBF*2;              // 81920 B
    const int ASM=(2*128+4*64)*QSTR*2;       // 73728 B
    cudaFuncSetAttribute(gemm_mma<0>,cudaFuncAttributeMaxDynamicSharedMemorySize,GSM);
    cudaFuncSetAttribute(gemm_mma<1>,cudaFuncAttributeMaxDynamicSharedMemorySize,GSM);
    cudaFuncSetAttribute(attn_mma,cudaFuncAttributeMaxDynamicSharedMemorySize,ASM);

    vsplit<<<(MM*EMB/2+255)/256,256>>>(x,(bf*)xh,(bf*)xl,MM*EMB);
    tsplit<<<dim3(C3/32,EMB/32),dim3(32,8)>>>(w_qkv,(bf*)wqh,(bf*)wql,EMB,C3);
    tsplit<<<dim3(EMB/32,EMB/32),dim3(32,8)>>>(w_proj,(bf*)wph,(bf*)wpl,EMB,EMB);

    gemm_mma<1><<<dim3(C3/128,MM/128),256,GSM>>>(
        (const bf*)xh,(const bf*)xl,(const bf*)wqh,(const bf*)wql,b_qkv,
        nullptr,(bf*)qhp,(bf*)qlp, MM,C3,EMB);

    attn_mma<<<dim3(TT/128,BB*HEADS),256,ASM>>>(
        (const bf*)qhp,(const bf*)qlp,(bf*)yhp,(bf*)ylp);

    gemm_mma<0><<<dim3(EMB/128,MM/128),256,GSM>>>(
        (const bf*)yhp,(const bf*)ylp,(const bf*)wph,(const bf*)wpl,b_proj,
        out,nullptr,nullptr, MM,EMB,EMB);
}

// round 4
// speedup vs baseline: 2.9361x; 1.0851x over previous
#include <cuda_runtime.h>
#include <cuda_bf16.h>
#include <math.h>

#define EMB 768
#define HEADS 12
#define TT 2048
#define BB 4
#define C3 (3*EMB)
#define MM (BB*TT)
typedef __nv_bfloat16 bf;

// ------------- scratch (device globals, allocation-free) -------------
__device__ __align__(16) bf g_xh[MM*EMB],  g_xl[MM*EMB];
__device__ __align__(16) bf g_wqh[C3*EMB], g_wql[C3*EMB];   // w_qkv^T [N][K]
__device__ __align__(16) bf g_wph[EMB*EMB],g_wpl[EMB*EMB];  // w_proj^T
__device__ __align__(16) bf g_qh[(size_t)MM*C3], g_ql[(size_t)MM*C3];
__device__ __align__(16) bf g_yh[MM*EMB],  g_yl[MM*EMB];

// ------------- helpers -------------
__device__ __forceinline__ void split2(float x, float y, unsigned &hi, unsigned &lo){
    __nv_bfloat16 a=__float2bfloat16(x), b=__float2bfloat16(y);
    hi=(unsigned)__bfloat16_as_ushort(a)|((unsigned)__bfloat16_as_ushort(b)<<16);
    __nv_bfloat16 c=__float2bfloat16(x-__bfloat162float(a));
    __nv_bfloat16 d=__float2bfloat16(y-__bfloat162float(b));
    lo=(unsigned)__bfloat16_as_ushort(c)|((unsigned)__bfloat16_as_ushort(d)<<16);
}
#define MMA(D,A,B) asm volatile("mma.sync.aligned.m16n8k16.row.col.f32.bf16.bf16.f32 " \
  "{%0,%1,%2,%3},{%4,%5,%6,%7},{%8,%9},{%0,%1,%2,%3};" \
  : "+f"(D[0]),"+f"(D[1]),"+f"(D[2]),"+f"(D[3]) \
  : "r"(A[0]),"r"(A[1]),"r"(A[2]),"r"(A[3]),"r"(B[0]),"r"(B[1]))
__device__ __forceinline__ void ldsm4(unsigned a, unsigned r[4]){
    asm volatile("ldmatrix.sync.aligned.m8n8.x4.shared.b16 {%0,%1,%2,%3},[%4];"
      :"=r"(r[0]),"=r"(r[1]),"=r"(r[2]),"=r"(r[3]):"r"(a));
}
__device__ __forceinline__ void ldsm4t(unsigned a, unsigned r[4]){
    asm volatile("ldmatrix.sync.aligned.m8n8.x4.trans.shared.b16 {%0,%1,%2,%3},[%4];"
      :"=r"(r[0]),"=r"(r[1]),"=r"(r[2]),"=r"(r[3]):"r"(a));
}
#define CPA(d,s) asm volatile("cp.async.cg.shared.global [%0],[%1],16;"::"r"(d),"l"(s))
#define CPCOMMIT() asm volatile("cp.async.commit_group;")

// ------------- conversion kernels -------------
__global__ void vsplit(const float* __restrict__ x, bf* hi, bf* lo, int n){
    int i=(blockIdx.x*blockDim.x+threadIdx.x)*2;
    if(i<n){ unsigned h,l; split2(x[i],x[i+1],h,l);
        *(unsigned*)(hi+i)=h; *(unsigned*)(lo+i)=l; }
}
__global__ void tsplit(const float* __restrict__ w, bf* th, bf* tl, int R, int C){
    __shared__ float t[32][33];
    int c0=blockIdx.x*32, r0=blockIdx.y*32, tx=threadIdx.x, ty=threadIdx.y;
    #pragma unroll
    for(int i=0;i<32;i+=8) t[ty+i][tx]=w[(size_t)(r0+ty+i)*C+c0+tx];
    __syncthreads();
    #pragma unroll
    for(int i=0;i<32;i+=8){
        float v=t[tx][ty+i];
        bf hv=__float2bfloat16(v);
        th[(size_t)(c0+ty+i)*R+r0+tx]=hv;
        tl[(size_t)(c0+ty+i)*R+r0+tx]=__float2bfloat16(v-__bfloat162float(hv));
    }
}

// ------------- GEMM: C[M,N] = (Ah+Al)[M,K] @ (Bh+Bl)[N,K]^T + bias -------------
// 3-stage cp.async pipeline, one __syncthreads per k-iter, term-pass MMA order.
#define SASTR 40
#define TILEBF (128*SASTR)
#define STAGEB (4*TILEBF*2)
template<int SPLITOUT>
__global__ __launch_bounds__(256,1) void gemm_mma(
    const bf* __restrict__ Ah, const bf* __restrict__ Al,
    const bf* __restrict__ Bh, const bf* __restrict__ Bl,
    const float* __restrict__ bias,
    float* __restrict__ Cf, bf* __restrict__ Ch, bf* __restrict__ Cl,
    int M, int N, int K)
{
    extern __shared__ bf sm[];
    const int tid=threadIdx.x, lane=tid&31, w=tid>>5;
    const int wm=(w>>2)*64, wn=(w&3)*32;
    const int bm=blockIdx.y*128, bn=blockIdx.x*128;
    unsigned sb0=(unsigned)__cvta_generic_to_shared(sm);
    float acc[4][4][4];
    #pragma unroll
    for(int a=0;a<4;a++)
      #pragma unroll
      for(int b=0;b<4;b++){acc[a][b][0]=0;acc[a][b][1]=0;acc[a][b][2]=0;acc[a][b][3]=0;}

    auto loadstage=[&](int st,int k0){
        unsigned base=sb0+st*STAGEB;
        #pragma unroll
        for(int i=0;i<2;i++){
            int c=tid+i*256, r=c>>2, kc=(c&3)*8;
            size_t ao=(size_t)(bm+r)*K+k0+kc, bo=(size_t)(bn+r)*K+k0+kc;
            unsigned so=(r*SASTR+kc)*2;
            CPA(base+so,            Ah+ao);
            CPA(base+TILEBF*2+so,   Al+ao);
            CPA(base+2*TILEBF*2+so, Bh+bo);
            CPA(base+3*TILEBF*2+so, Bl+bo);
        }
        CPCOMMIT();
    };

    const int NIT=K/32;
    loadstage(0,0); loadstage(1,32);
    for(int it=0;it<NIT;it++){
        if(it+1<NIT) asm volatile("cp.async.wait_group 1;");
        else         asm volatile("cp.async.wait_group 0;");
        __syncthreads();
        if(it+2<NIT) loadstage((it+2)%3,(it+2)*32);
        unsigned sb=sb0+(it%3)*STAGEB;
        #pragma unroll
        for(int ks=0;ks<2;ks++){
            int kb=ks*16+(lane>>4)*8;
            unsigned ah[4][4], al[4][4], bch[4][2], bcl[4][2];
            #pragma unroll
            for(int mf=0;mf<4;mf++){
                int row=wm+mf*16+(lane&15);
                ldsm4(sb+(row*SASTR+kb)*2, ah[mf]);
                ldsm4(sb+TILEBF*2+(row*SASTR+kb)*2, al[mf]);
            }
            #pragma unroll
            for(int nb=0;nb<2;nb++){
                unsigned t[4];
                int row=wn+nb*16+(lane&15);
                ldsm4(sb+2*TILEBF*2+(row*SASTR+kb)*2, t);
                bch[2*nb][0]=t[0]; bch[2*nb][1]=t[2];
                bch[2*nb+1][0]=t[1]; bch[2*nb+1][1]=t[3];
                ldsm4(sb+3*TILEBF*2+(row*SASTR+kb)*2, t);
                bcl[2*nb][0]=t[0]; bcl[2*nb][1]=t[2];
                bcl[2*nb+1][0]=t[1]; bcl[2*nb+1][1]=t[3];
            }
            #pragma unroll
            for(int mf=0;mf<4;mf++)
                #pragma unroll
                for(int nf=0;nf<4;nf++) MMA(acc[mf][nf],ah[mf],bch[nf]);
            #pragma unroll
            for(int mf=0;mf<4;mf++)
                #pragma unroll
                for(int nf=0;nf<4;nf++) MMA(acc[mf][nf],ah[mf],bcl[nf]);
            #pragma unroll
            for(int mf=0;mf<4;mf++)
                #pragma unroll
                for(int nf=0;nf<4;nf++) MMA(acc[mf][nf],al[mf],bch[nf]);
        }
    }
    int g=lane>>2, tg=(lane&3)*2;
    #pragma unroll
    for(int mf=0;mf<4;mf++){
        int r0=bm+wm+mf*16+g;
        #pragma unroll
        for(int nf=0;nf<4;nf++){
            int col=bn+wn+nf*8+tg;
            float b0=bias[col], b1=bias[col+1];
            float v0=acc[mf][nf][0]+b0, v1=acc[mf][nf][1]+b1;
            float v2=acc[mf][nf][2]+b0, v3=acc[mf][nf][3]+b1;
            if(SPLITOUT){
                unsigned hi,lo;
                split2(v0,v1,hi,lo);
                *(unsigned*)(Ch+(size_t)r0*N+col)=hi; *(unsigned*)(Cl+(size_t)r0*N+col)=lo;
                split2(v2,v3,hi,lo);
                *(unsigned*)(Ch+(size_t)(r0+8)*N+col)=hi; *(unsigned*)(Cl+(size_t)(r0+8)*N+col)=lo;
            }else{
                *(float2*)(Cf+(size_t)r0*N+col)=make_float2(v0,v1);
                *(float2*)(Cf+(size_t)(r0+8)*N+col)=make_float2(v2,v3);
            }
        }
    }
}

// ------------- causal flash attention, bf16 split mma, double-buffered K/V -------------
#define QSTR 72
#define SKV (4*64*QSTR)           // one K/V stage (elements)
#define KV0 (2*128*QSTR)          // after Q hi/lo
__global__ __launch_bounds__(256,1) void attn_mma(
    const bf* __restrict__ qh, const bf* __restrict__ ql,
    bf* __restrict__ yh, bf* __restrict__ yl)
{
    extern __shared__ bf sm[];
    const int tid=threadIdx.x, lane=tid&31, w=tid>>5;
    const int qt=gridDim.x-1-blockIdx.x, qb=qt*128;
    const int bh_=blockIdx.y, b=bh_/HEADS, h=bh_-b*HEADS;
    const size_t rowbase=(size_t)b*TT*C3+h*64;
    unsigned sb=(unsigned)__cvta_generic_to_shared(sm);

    auto loadKV=[&](int st,int kb){
        unsigned base=sb+(KV0+st*SKV)*2;
        #pragma unroll
        for(int i=0;i<2;i++){
            int c=tid+i*256, r=c>>3, kc=(c&7)*8;
            size_t go=rowbase+(size_t)(kb+r)*C3+kc;
            unsigned so=(r*QSTR+kc)*2;
            CPA(base+so,               qh+go+EMB);
            CPA(base+64*QSTR*2+so,     ql+go+EMB);
            CPA(base+2*64*QSTR*2+so,   qh+go+2*EMB);
            CPA(base+3*64*QSTR*2+so,   ql+go+2*EMB);
        }
        CPCOMMIT();
    };

    loadKV(0,0);   // overlap with Q staging

    #pragma unroll
    for(int i=0;i<4;i++){
        int c=tid+i*256, r=c>>3, kc=(c&7)*8;
        *(uint4*)(sm+r*QSTR+kc)          =*(const uint4*)(qh+rowbase+(size_t)(qb+r)*C3+kc);
        *(uint4*)(sm+128*QSTR+r*QSTR+kc) =*(const uint4*)(ql+rowbase+(size_t)(qb+r)*C3+kc);
    }
    __syncthreads();
    unsigned qfh[4][4], qfl[4][4];
    {
        int row=w*16+(lane&15);
        #pragma unroll
        for(int ks=0;ks<4;ks++){
            int kb=ks*16+(lane>>4)*8;
            ldsm4(sb+(row*QSTR+kb)*2, qfh[ks]);
            ldsm4(sb+(128*QSTR+row*QSTR+kb)*2, qfl[ks]);
        }
    }
    float m0=-1e30f,m1=-1e30f,l0=0.f,l1=0.f,o[8][4];
    #pragma unroll
    for(int i=0;i<8;i++){o[i][0]=0;o[i][1]=0;o[i][2]=0;o[i][3]=0;}
    const float SC=0.18033688f;  // 0.125 * log2(e)
    const int g=lane>>2, tg=(lane&3)*2;
    const int nkt=qb/64+2;

    for(int kt=0;kt<nkt;kt++){
        int kb=kt*64;
        asm volatile("cp.async.wait_group 0;");
        __syncthreads();
        if(kt+1<nkt) loadKV((kt+1)&1,(kt+1)*64);
        unsigned kvb=sb+(KV0+(kt&1)*SKV)*2;
        unsigned KH=kvb, KL=kvb+64*QSTR*2, VH=kvb+2*64*QSTR*2, VL=kvb+3*64*QSTR*2;

        float s[8][4];
        #pragma unroll
        for(int i=0;i<8;i++){s[i][0]=0;s[i][1]=0;s[i][2]=0;s[i][3]=0;}
        #pragma unroll
        for(int ks=0;ks<4;ks++){
            int kbb=ks*16+(lane>>4)*8;
            unsigned kch[8][2], kcl[8][2];
            #pragma unroll
            for(int nb=0;nb<4;nb++){
                unsigned t[4];
                int row=nb*16+(lane&15);
                ldsm4(KH+(row*QSTR+kbb)*2,t);
                kch[2*nb][0]=t[0]; kch[2*nb][1]=t[2];
                kch[2*nb+1][0]=t[1]; kch[2*nb+1][1]=t[3];
                ldsm4(KL+(row*QSTR+kbb)*2,t);
                kcl[2*nb][0]=t[0]; kcl[2*nb][1]=t[2];
                kcl[2*nb+1][0]=t[1]; kcl[2*nb+1][1]=t[3];
            }
            #pragma unroll
            for(int nf=0;nf<8;nf++) MMA(s[nf],qfh[ks],kch[nf]);
            #pragma unroll
            for(int nf=0;nf<8;nf++) MMA(s[nf],qfh[ks],kcl[nf]);
            #pragma unroll
            for(int nf=0;nf<8;nf++) MMA(s[nf],qfl[ks],kch[nf]);
        }
        bool domask=(kb+63 > qb+w*16);
        #pragma unroll
        for(int nf=0;nf<8;nf++)
            #pragma unroll
            for(int r=0;r<4;r++){
                float v=s[nf][r]*SC;
                if(domask){
                    int key=kb+nf*8+tg+(r&1);
                    int qr=qb+w*16+g+((r>>1)<<3);
                    if(key>qr) v=-1e30f;
                }
                s[nf][r]=v;
            }
        float mx0=-1e30f,mx1=-1e30f;
        #pragma unroll
        for(int nf=0;nf<8;nf++){
            mx0=fmaxf(mx0,fmaxf(s[nf][0],s[nf][1]));
            mx1=fmaxf(mx1,fmaxf(s[nf][2],s[nf][3]));
        }
        mx0=fmaxf(mx0,__shfl_xor_sync(0xffffffffu,mx0,1));
        mx0=fmaxf(mx0,__shfl_xor_sync(0xffffffffu,mx0,2));
        mx1=fmaxf(mx1,__shfl_xor_sync(0xffffffffu,mx1,1));
        mx1=fmaxf(mx1,__shfl_xor_sync(0xffffffffu,mx1,2));
        float nm0=fmaxf(m0,mx0), nm1=fmaxf(m1,mx1);
        float a0=exp2f(m0-nm0), a1=exp2f(m1-nm1);
        m0=nm0; m1=nm1;
        float rs0=0.f, rs1=0.f;
        #pragma unroll
        for(int nf=0;nf<8;nf++){
            s[nf][0]=exp2f(s[nf][0]-nm0); s[nf][1]=exp2f(s[nf][1]-nm0);
            s[nf][2]=exp2f(s[nf][2]-nm1); s[nf][3]=exp2f(s[nf][3]-nm1);
            rs0+=s[nf][0]+s[nf][1]; rs1+=s[nf][2]+s[nf][3];
        }
        rs0+=__shfl_xor_sync(0xffffffffu,rs0,1); rs0+=__shfl_xor_sync(0xffffffffu,rs0,2);
        rs1+=__shfl_xor_sync(0xffffffffu,rs1,1); rs1+=__shfl_xor_sync(0xffffffffu,rs1,2);
        l0=l0*a0+rs0; l1=l1*a1+rs1;
        #pragma unroll
        for(int i=0;i<8;i++){o[i][0]*=a0;o[i][1]*=a0;o[i][2]*=a1;o[i][3]*=a1;}
        #pragma unroll
        for(int ks=0;ks<4;ks++){
            unsigned ph[4],pl[4];
            split2(s[2*ks][0],s[2*ks][1],ph[0],pl[0]);
            split2(s[2*ks][2],s[2*ks][3],ph[1],pl[1]);
            split2(s[2*ks+1][0],s[2*ks+1][1],ph[2],pl[2]);
            split2(s[2*ks+1][2],s[2*ks+1][3],ph[3],pl[3]);
            int row=ks*16+(lane&15);
            unsigned vch[8][2], vcl[8][2];
            #pragma unroll
            for(int db=0;db<4;db++){
                unsigned t[4];
                int dbb=db*16+(lane>>4)*8;
                ldsm4t(VH+(row*QSTR+dbb)*2,t);
                vch[2*db][0]=t[0]; vch[2*db][1]=t[1];
                vch[2*db+1][0]=t[2]; vch[2*db+1][1]=t[3];
                ldsm4t(VL+(row*QSTR+dbb)*2,t);
                vcl[2*db][0]=t[0]; vcl[2*db][1]=t[1];
                vcl[2*db+1][0]=t[2]; vcl[2*db+1][1]=t[3];
            }
            #pragma unroll
            for(int nf=0;nf<8;nf++) MMA(o[nf],ph,vch[nf]);
            #pragma unroll
            for(int nf=0;nf<8;nf++) MMA(o[nf],ph,vcl[nf]);
            #pragma unroll
            for(int nf=0;nf<8;nf++) MMA(o[nf],pl,vch[nf]);
        }
    }
    float i0=1.f/l0, i1=1.f/l1;
    #pragma unroll
    for(int dn=0;dn<8;dn++){
        int col=h*64+dn*8+tg;
        size_t r0=(size_t)b*TT+qb+w*16+g;
        unsigned hi,lo;
        split2(o[dn][0]*i0,o[dn][1]*i0,hi,lo);
        *(unsigned*)(yh+r0*EMB+col)=hi; *(unsigned*)(yl+r0*EMB+col)=lo;
        split2(o[dn][2]*i1,o[dn][3]*i1,hi,lo);
        *(unsigned*)(yh+(r0+8)*EMB+col)=hi; *(unsigned*)(yl+(r0+8)*EMB+col)=lo;
    }
}

// ------------- launch -------------
extern "C" void kernel_launch(void* const* d_in, const int* in_sizes, int n_in,
                              void* d_out, int out_size)
{
    const float* x=(const float*)d_in[0];
    const float* w_qkv=(const float*)d_in[1];
    const float* b_qkv=(const float*)d_in[2];
    const float* w_proj=(const float*)d_in[3];
    const float* b_proj=(const float*)d_in[4];
    float* out=(float*)d_out;

    void *xh,*xl,*wqh,*wql,*wph,*wpl,*qhp,*qlp,*yhp,*ylp;
    cudaGetSymbolAddress(&xh,g_xh);   cudaGetSymbolAddress(&xl,g_xl);
    cudaGetSymbolAddress(&wqh,g_wqh); cudaGetSymbolAddress(&wql,g_wql);
    cudaGetSymbolAddress(&wph,g_wph); cudaGetSymbolAddress(&wpl,g_wpl);
    cudaGetSymbolAddress(&qhp,g_qh);  cudaGetSymbolAddress(&qlp,g_ql);
    cudaGetSymbolAddress(&yhp,g_yh);  cudaGetSymbolAddress(&ylp,g_yl);

    const int GSM=3*STAGEB;                       // 122880 B
    const int ASM=(2*128*QSTR+2*SKV)*2;           // 110592 B
    cudaFuncSetAttribute(gemm_mma<0>,cudaFuncAttributeMaxDynamicSharedMemorySize,GSM);
    cudaFuncSetAttribute(gemm_mma<1>,cudaFuncAttributeMaxDynamicSharedMemorySize,GSM);
    cudaFuncSetAttribute(attn_mma,cudaFuncAttributeMaxDynamicSharedMemorySize,ASM);

    vsplit<<<(MM*EMB/2+255)/256,256>>>(x,(bf*)xh,(bf*)xl,MM*EMB);
    tsplit<<<dim3(C3/32,EMB/32),dim3(32,8)>>>(w_qkv,(bf*)wqh,(bf*)wql,EMB,C3);
    tsplit<<<dim3(EMB/32,EMB/32),dim3(32,8)>>>(w_proj,(bf*)wph,(bf*)wpl,EMB,EMB);

    gemm_mma<1><<<dim3(C3/128,MM/128),256,GSM>>>(
        (const bf*)xh,(const bf*)xl,(const bf*)wqh,(const bf*)wql,b_qkv,
        nullptr,(bf*)qhp,(bf*)qlp, MM,C3,EMB);

    attn_mma<<<dim3(TT/128,BB*HEADS),256,ASM>>>(
        (const bf*)qhp,(const bf*)qlp,(bf*)yhp,(bf*)ylp);

    gemm_mma<0><<<dim3(EMB/128,MM/128),256,GSM>>>(
        (const bf*)yhp,(const bf*)ylp,(const bf*)wph,(const bf*)wpl,b_proj,
        out,nullptr,nullptr, MM,EMB,EMB);
}

// round 6
// speedup vs baseline: 2.9754x; 1.0134x over previous
#include <cuda_runtime.h>
#include <cuda_bf16.h>
#include <math.h>

#define EMB 768
#define HEADS 12
#define TT 2048
#define BB 4
#define C3 (3*EMB)
#define MM (BB*TT)
typedef __nv_bfloat16 bf;

// ------------- scratch (device globals, allocation-free) -------------
__device__ __align__(16) bf g_xh[MM*EMB],  g_xl[MM*EMB];
__device__ __align__(16) bf g_wqh[C3*EMB], g_wql[C3*EMB];   // w_qkv^T [N][K]
__device__ __align__(16) bf g_wph[EMB*EMB],g_wpl[EMB*EMB];  // w_proj^T
__device__ __align__(16) bf g_qh[(size_t)MM*C3], g_ql[(size_t)MM*C3];
__device__ __align__(16) bf g_yh[MM*EMB],  g_yl[MM*EMB];

// ------------- helpers -------------
__device__ __forceinline__ void split2(float x, float y, unsigned &hi, unsigned &lo){
    __nv_bfloat16 a=__float2bfloat16(x), b=__float2bfloat16(y);
    hi=(unsigned)__bfloat16_as_ushort(a)|((unsigned)__bfloat16_as_ushort(b)<<16);
    __nv_bfloat16 c=__float2bfloat16(x-__bfloat162float(a));
    __nv_bfloat16 d=__float2bfloat16(y-__bfloat162float(b));
    lo=(unsigned)__bfloat16_as_ushort(c)|((unsigned)__bfloat16_as_ushort(d)<<16);
}
#define MMA(D,A,B) asm volatile("mma.sync.aligned.m16n8k16.row.col.f32.bf16.bf16.f32 " \
  "{%0,%1,%2,%3},{%4,%5,%6,%7},{%8,%9},{%0,%1,%2,%3};" \
  : "+f"(D[0]),"+f"(D[1]),"+f"(D[2]),"+f"(D[3]) \
  : "r"(A[0]),"r"(A[1]),"r"(A[2]),"r"(A[3]),"r"(B[0]),"r"(B[1]))
__device__ __forceinline__ void ldsm4(unsigned a, unsigned r[4]){
    asm volatile("ldmatrix.sync.aligned.m8n8.x4.shared.b16 {%0,%1,%2,%3},[%4];"
      :"=r"(r[0]),"=r"(r[1]),"=r"(r[2]),"=r"(r[3]):"r"(a));
}
__device__ __forceinline__ void ldsm4t(unsigned a, unsigned r[4]){
    asm volatile("ldmatrix.sync.aligned.m8n8.x4.trans.shared.b16 {%0,%1,%2,%3},[%4];"
      :"=r"(r[0]),"=r"(r[1]),"=r"(r[2]),"=r"(r[3]):"r"(a));
}
#define CPA(d,s) asm volatile("cp.async.cg.shared.global [%0],[%1],16;"::"r"(d),"l"(s))
#define CPCOMMIT() asm volatile("cp.async.commit_group;")

// ------------- conversion kernels -------------
__global__ void vsplit(const float* __restrict__ x, bf* hi, bf* lo, int n){
    int i=(blockIdx.x*blockDim.x+threadIdx.x)*2;
    if(i<n){ unsigned h,l; split2(x[i],x[i+1],h,l);
        *(unsigned*)(hi+i)=h; *(unsigned*)(lo+i)=l; }
}
__global__ void tsplit(const float* __restrict__ w, bf* th, bf* tl, int R, int C){
    __shared__ float t[32][33];
    int c0=blockIdx.x*32, r0=blockIdx.y*32, tx=threadIdx.x, ty=threadIdx.y;
    #pragma unroll
    for(int i=0;i<32;i+=8) t[ty+i][tx]=w[(size_t)(r0+ty+i)*C+c0+tx];
    __syncthreads();
    #pragma unroll
    for(int i=0;i<32;i+=8){
        float v=t[tx][ty+i];
        bf hv=__float2bfloat16(v);
        th[(size_t)(c0+ty+i)*R+r0+tx]=hv;
        tl[(size_t)(c0+ty+i)*R+r0+tx]=__float2bfloat16(v-__bfloat162float(hv));
    }
}

// ------------- GEMM: C[M,N] = (Ah+Al)[M,K] @ (Bh+Bl)[N,K]^T + bias -------------
// 512 threads, 128x128 tile, 16 warps (4x4), 32x32 per warp, 3-stage cp.async.
#define SASTR 40
#define TILEA (128*SASTR)
#define STAGEB (4*TILEA*2)
template<int SPLITOUT>
__global__ __launch_bounds__(512,1) void gemm_mma(
    const bf* __restrict__ Ah, const bf* __restrict__ Al,
    const bf* __restrict__ Bh, const bf* __restrict__ Bl,
    const float* __restrict__ bias,
    float* __restrict__ Cf, bf* __restrict__ Ch, bf* __restrict__ Cl,
    int M, int N, int K)
{
    extern __shared__ bf sm[];
    const int tid=threadIdx.x, lane=tid&31, w=tid>>5;
    const int wm=(w>>2)*32, wn=(w&3)*32;
    const int bm=blockIdx.y*128, bn=blockIdx.x*128;
    unsigned sb0=(unsigned)__cvta_generic_to_shared(sm);
    float acc[2][4][4];
    #pragma unroll
    for(int a=0;a<2;a++)
      #pragma unroll
      for(int b=0;b<4;b++){acc[a][b][0]=0;acc[a][b][1]=0;acc[a][b][2]=0;acc[a][b][3]=0;}

    auto loadstage=[&](int st,int k0){
        unsigned base=sb0+st*STAGEB;
        int r=tid>>2, kc=(tid&3)*8;
        size_t ao=(size_t)(bm+r)*K+k0+kc, bo=(size_t)(bn+r)*K+k0+kc;
        unsigned so=(r*SASTR+kc)*2;
        CPA(base+so,           Ah+ao);
        CPA(base+TILEA*2+so,   Al+ao);
        CPA(base+2*TILEA*2+so, Bh+bo);
        CPA(base+3*TILEA*2+so, Bl+bo);
        CPCOMMIT();
    };

    const int NIT=K/32;
    loadstage(0,0); loadstage(1,32);
    for(int it=0;it<NIT;it++){
        if(it+1<NIT) asm volatile("cp.async.wait_group 1;");
        else         asm volatile("cp.async.wait_group 0;");
        __syncthreads();
        if(it+2<NIT) loadstage((it+2)%3,(it+2)*32);
        unsigned sb=sb0+(it%3)*STAGEB;
        #pragma unroll
        for(int ks=0;ks<2;ks++){
            int kb=ks*16+(lane>>4)*8;
            unsigned ah[2][4], al[2][4], bch[4][2], bcl[4][2];
            #pragma unroll
            for(int mf=0;mf<2;mf++){
                int row=wm+mf*16+(lane&15);
                ldsm4(sb+(row*SASTR+kb)*2, ah[mf]);
                ldsm4(sb+TILEA*2+(row*SASTR+kb)*2, al[mf]);
            }
            #pragma unroll
            for(int nb=0;nb<2;nb++){
                unsigned t[4];
                int row=wn+nb*16+(lane&15);
                ldsm4(sb+2*TILEA*2+(row*SASTR+kb)*2, t);
                bch[2*nb][0]=t[0]; bch[2*nb][1]=t[2];
                bch[2*nb+1][0]=t[1]; bch[2*nb+1][1]=t[3];
                ldsm4(sb+3*TILEA*2+(row*SASTR+kb)*2, t);
                bcl[2*nb][0]=t[0]; bcl[2*nb][1]=t[2];
                bcl[2*nb+1][0]=t[1]; bcl[2*nb+1][1]=t[3];
            }
            #pragma unroll
            for(int mf=0;mf<2;mf++)
                #pragma unroll
                for(int nf=0;nf<4;nf++) MMA(acc[mf][nf],ah[mf],bch[nf]);
            #pragma unroll
            for(int mf=0;mf<2;mf++)
                #pragma unroll
                for(int nf=0;nf<4;nf++) MMA(acc[mf][nf],ah[mf],bcl[nf]);
            #pragma unroll
            for(int mf=0;mf<2;mf++)
                #pragma unroll
                for(int nf=0;nf<4;nf++) MMA(acc[mf][nf],al[mf],bch[nf]);
        }
    }
    int g=lane>>2, tg=(lane&3)*2;
    #pragma unroll
    for(int mf=0;mf<2;mf++){
        int r0=bm+wm+mf*16+g;
        #pragma unroll
        for(int nf=0;nf<4;nf++){
            int col=bn+wn+nf*8+tg;
            float b0=bias[col], b1=bias[col+1];
            float v0=acc[mf][nf][0]+b0, v1=acc[mf][nf][1]+b1;
            float v2=acc[mf][nf][2]+b0, v3=acc[mf][nf][3]+b1;
            if(SPLITOUT){
                unsigned hi,lo;
                split2(v0,v1,hi,lo);
                *(unsigned*)(Ch+(size_t)r0*N+col)=hi; *(unsigned*)(Cl+(size_t)r0*N+col)=lo;
                split2(v2,v3,hi,lo);
                *(unsigned*)(Ch+(size_t)(r0+8)*N+col)=hi; *(unsigned*)(Cl+(size_t)(r0+8)*N+col)=lo;
            }else{
                *(float2*)(Cf+(size_t)r0*N+col)=make_float2(v0,v1);
                *(float2*)(Cf+(size_t)(r0+8)*N+col)=make_float2(v2,v3);
            }
        }
    }
}

// ------------- causal flash attention, bf16 split mma, double-buffered K/V ----
#define QSTR 72
#define SKV (4*64*QSTR)
#define KV0 (2*128*QSTR)
__global__ __launch_bounds__(256,1) void attn_mma(
    const bf* __restrict__ qh, const bf* __restrict__ ql,
    bf* __restrict__ yh, bf* __restrict__ yl)
{
    extern __shared__ bf sm[];
    const int tid=threadIdx.x, lane=tid&31, w=tid>>5;
    const int qt=gridDim.x-1-blockIdx.x, qb=qt*128;
    const int bh_=blockIdx.y, b=bh_/HEADS, h=bh_-b*HEADS;
    const size_t rowbase=(size_t)b*TT*C3+h*64;
    unsigned sb=(unsigned)__cvta_generic_to_shared(sm);

    auto loadKV=[&](int st,int kb){
        unsigned base=sb+(KV0+st*SKV)*2;
        #pragma unroll
        for(int i=0;i<2;i++){
            int c=tid+i*256, r=c>>3, kc=(c&7)*8;
            size_t go=rowbase+(size_t)(kb+r)*C3+kc;
            unsigned so=(r*QSTR+kc)*2;
            CPA(base+so,               qh+go+EMB);
            CPA(base+64*QSTR*2+so,     ql+go+EMB);
            CPA(base+2*64*QSTR*2+so,   qh+go+2*EMB);
            CPA(base+3*64*QSTR*2+so,   ql+go+2*EMB);
        }
        CPCOMMIT();
    };

    loadKV(0,0);

    #pragma unroll
    for(int i=0;i<4;i++){
        int c=tid+i*256, r=c>>3, kc=(c&7)*8;
        *(uint4*)(sm+r*QSTR+kc)          =*(const uint4*)(qh+rowbase+(size_t)(qb+r)*C3+kc);
        *(uint4*)(sm+128*QSTR+r*QSTR+kc) =*(const uint4*)(ql+rowbase+(size_t)(qb+r)*C3+kc);
    }
    __syncthreads();
    unsigned qfh[4][4], qfl[4][4];
    {
        int row=w*16+(lane&15);
        #pragma unroll
        for(int ks=0;ks<4;ks++){
            int kb=ks*16+(lane>>4)*8;
            ldsm4(sb+(row*QSTR+kb)*2, qfh[ks]);
            ldsm4(sb+(128*QSTR+row*QSTR+kb)*2, qfl[ks]);
        }
    }
    float m0=-1e30f,m1=-1e30f,l0=0.f,l1=0.f,o[8][4];
    #pragma unroll
    for(int i=0;i<8;i++){o[i][0]=0;o[i][1]=0;o[i][2]=0;o[i][3]=0;}
    const float SC=0.18033688f;
    const int g=lane>>2, tg=(lane&3)*2;
    const int nkt=qb/64+2;

    for(int kt=0;kt<nkt;kt++){
        int kb=kt*64;
        asm volatile("cp.async.wait_group 0;");
        __syncthreads();
        if(kt+1<nkt) loadKV((kt+1)&1,(kt+1)*64);
        unsigned kvb=sb+(KV0+(kt&1)*SKV)*2;
        unsigned KH=kvb, KL=kvb+64*QSTR*2, VH=kvb+2*64*QSTR*2, VL=kvb+3*64*QSTR*2;

        float s[8][4];
        #pragma unroll
        for(int i=0;i<8;i++){s[i][0]=0;s[i][1]=0;s[i][2]=0;s[i][3]=0;}
        #pragma unroll
        for(int ks=0;ks<4;ks++){
            int kbb=ks*16+(lane>>4)*8;
            unsigned kch[8][2], kcl[8][2];
            #pragma unroll
            for(int nb=0;nb<4;nb++){
                unsigned t[4];
                int row=nb*16+(lane&15);
                ldsm4(KH+(row*QSTR+kbb)*2,t);
                kch[2*nb][0]=t[0]; kch[2*nb][1]=t[2];
                kch[2*nb+1][0]=t[1]; kch[2*nb+1][1]=t[3];
                ldsm4(KL+(row*QSTR+kbb)*2,t);
                kcl[2*nb][0]=t[0]; kcl[2*nb][1]=t[2];
                kcl[2*nb+1][0]=t[1]; kcl[2*nb+1][1]=t[3];
            }
            #pragma unroll
            for(int nf=0;nf<8;nf++) MMA(s[nf],qfh[ks],kch[nf]);
            #pragma unroll
            for(int nf=0;nf<8;nf++) MMA(s[nf],qfh[ks],kcl[nf]);
            #pragma unroll
            for(int nf=0;nf<8;nf++) MMA(s[nf],qfl[ks],kch[nf]);
        }
        bool domask=(kb+63 > qb+w*16);
        #pragma unroll
        for(int nf=0;nf<8;nf++)
            #pragma unroll
            for(int r=0;r<4;r++){
                float v=s[nf][r]*SC;
                if(domask){
                    int key=kb+nf*8+tg+(r&1);
                    int qr=qb+w*16+g+((r>>1)<<3);
                    if(key>qr) v=-1e30f;
                }
                s[nf][r]=v;
            }
        float mx0=-1e30f,mx1=-1e30f;
        #pragma unroll
        for(int nf=0;nf<8;nf++){
            mx0=fmaxf(mx0,fmaxf(s[nf][0],s[nf][1]));
            mx1=fmaxf(mx1,fmaxf(s[nf][2],s[nf][3]));
        }
        mx0=fmaxf(mx0,__shfl_xor_sync(0xffffffffu,mx0,1));
        mx0=fmaxf(mx0,__shfl_xor_sync(0xffffffffu,mx0,2));
        mx1=fmaxf(mx1,__shfl_xor_sync(0xffffffffu,mx1,1));
        mx1=fmaxf(mx1,__shfl_xor_sync(0xffffffffu,mx1,2));
        float nm0=fmaxf(m0,mx0), nm1=fmaxf(m1,mx1);
        float a0=exp2f(m0-nm0), a1=exp2f(m1-nm1);
        m0=nm0; m1=nm1;
        float rs0=0.f, rs1=0.f;
        #pragma unroll
        for(int nf=0;nf<8;nf++){
            s[nf][0]=exp2f(s[nf][0]-nm0); s[nf][1]=exp2f(s[nf][1]-nm0);
            s[nf][2]=exp2f(s[nf][2]-nm1); s[nf][3]=exp2f(s[nf][3]-nm1);
            rs0+=s[nf][0]+s[nf][1]; rs1+=s[nf][2]+s[nf][3];
        }
        rs0+=__shfl_xor_sync(0xffffffffu,rs0,1); rs0+=__shfl_xor_sync(0xffffffffu,rs0,2);
        rs1+=__shfl_xor_sync(0xffffffffu,rs1,1); rs1+=__shfl_xor_sync(0xffffffffu,rs1,2);
        l0=l0*a0+rs0; l1=l1*a1+rs1;
        #pragma unroll
        for(int i=0;i<8;i++){o[i][0]*=a0;o[i][1]*=a0;o[i][2]*=a1;o[i][3]*=a1;}
        #pragma unroll
        for(int ks=0;ks<4;ks++){
            unsigned ph[4],pl[4];
            split2(s[2*ks][0],s[2*ks][1],ph[0],pl[0]);
            split2(s[2*ks][2],s[2*ks][3],ph[1],pl[1]);
            split2(s[2*ks+1][0],s[2*ks+1][1],ph[2],pl[2]);
            split2(s[2*ks+1][2],s[2*ks+1][3],ph[3],pl[3]);
            int row=ks*16+(lane&15);
            unsigned vch[8][2], vcl[8][2];
            #pragma unroll
            for(int db=0;db<4;db++){
                unsigned t[4];
                int dbb=db*16+(lane>>4)*8;
                ldsm4t(VH+(row*QSTR+dbb)*2,t);
                vch[2*db][0]=t[0]; vch[2*db][1]=t[1];
                vch[2*db+1][0]=t[2]; vch[2*db+1][1]=t[3];
                ldsm4t(VL+(row*QSTR+dbb)*2,t);
                vcl[2*db][0]=t[0]; vcl[2*db][1]=t[1];
                vcl[2*db+1][0]=t[2]; vcl[2*db+1][1]=t[3];
            }
            #pragma unroll
            for(int nf=0;nf<8;nf++) MMA(o[nf],ph,vch[nf]);
            #pragma unroll
            for(int nf=0;nf<8;nf++) MMA(o[nf],ph,vcl[nf]);
            #pragma unroll
            for(int nf=0;nf<8;nf++) MMA(o[nf],pl,vch[nf]);
        }
    }
    float i0=1.f/l0, i1=1.f/l1;
    #pragma unroll
    for(int dn=0;dn<8;dn++){
        int col=h*64+dn*8+tg;
        size_t r0=(size_t)b*TT+qb+w*16+g;
        unsigned hi,lo;
        split2(o[dn][0]*i0,o[dn][1]*i0,hi,lo);
        *(unsigned*)(yh+r0*EMB+col)=hi; *(unsigned*)(yl+r0*EMB+col)=lo;
        split2(o[dn][2]*i1,o[dn][3]*i1,hi,lo);
        *(unsigned*)(yh+(r0+8)*EMB+col)=hi; *(unsigned*)(yl+(r0+8)*EMB+col)=lo;
    }
}

// ------------- launch -------------
extern "C" void kernel_launch(void* const* d_in, const int* in_sizes, int n_in,
                              void* d_out, int out_size)
{
    const float* x=(const float*)d_in[0];
    const float* w_qkv=(const float*)d_in[1];
    const float* b_qkv=(const float*)d_in[2];
    const float* w_proj=(const float*)d_in[3];
    const float* b_proj=(const float*)d_in[4];
    float* out=(float*)d_out;

    void *xh,*xl,*wqh,*wql,*wph,*wpl,*qhp,*qlp,*yhp,*ylp;
    cudaGetSymbolAddress(&xh,g_xh);   cudaGetSymbolAddress(&xl,g_xl);
    cudaGetSymbolAddress(&wqh,g_wqh); cudaGetSymbolAddress(&wql,g_wql);
    cudaGetSymbolAddress(&wph,g_wph); cudaGetSymbolAddress(&wpl,g_wpl);
    cudaGetSymbolAddress(&qhp,g_qh);  cudaGetSymbolAddress(&qlp,g_ql);
    cudaGetSymbolAddress(&yhp,g_yh);  cudaGetSymbolAddress(&ylp,g_yl);

    const int GSM=3*STAGEB;                       // 122880 B
    const int ASM=(2*128*QSTR+2*SKV)*2;           // 110592 B
    cudaFuncSetAttribute(gemm_mma<0>,cudaFuncAttributeMaxDynamicSharedMemorySize,GSM);
    cudaFuncSetAttribute(gemm_mma<1>,cudaFuncAttributeMaxDynamicSharedMemorySize,GSM);
    cudaFuncSetAttribute(attn_mma,cudaFuncAttributeMaxDynamicSharedMemorySize,ASM);

    vsplit<<<(MM*EMB/2+255)/256,256>>>(x,(bf*)xh,(bf*)xl,MM*EMB);
    tsplit<<<dim3(C3/32,EMB/32),dim3(32,8)>>>(w_qkv,(bf*)wqh,(bf*)wql,EMB,C3);
    tsplit<<<dim3(EMB/32,EMB/32),dim3(32,8)>>>(w_proj,(bf*)wph,(bf*)wpl,EMB,EMB);

    gemm_mma<1><<<dim3(C3/128,MM/128),512,GSM>>>(
        (const bf*)xh,(const bf*)xl,(const bf*)wqh,(const bf*)wql,b_qkv,
        nullptr,(bf*)qhp,(bf*)qlp, MM,C3,EMB);

    attn_mma<<<dim3(TT/128,BB*HEADS),256,ASM>>>(
        (const bf*)qhp,(const bf*)qlp,(bf*)yhp,(bf*)ylp);

    gemm_mma<0><<<dim3(EMB/128,MM/128),512,GSM>>>(
        (const bf*)yhp,(const bf*)ylp,(const bf*)wph,(const bf*)wpl,b_proj,
        out,nullptr,nullptr, MM,EMB,EMB);
}

// round 7
// speedup vs baseline: 3.0961x; 1.0406x over previous
#include <cuda_runtime.h>
#include <cuda_bf16.h>
#include <math.h>

#define EMB 768
#define HEADS 12
#define TT 2048
#define BB 4
#define C3 (3*EMB)
#define MM (BB*TT)
typedef __nv_bfloat16 bf;

// ------------- scratch (device globals, allocation-free) -------------
__device__ __align__(16) bf g_xh[MM*EMB],  g_xl[MM*EMB];
__device__ __align__(16) bf g_wqh[C3*EMB], g_wql[C3*EMB];   // w_qkv^T [N][K]
__device__ __align__(16) bf g_wph[EMB*EMB],g_wpl[EMB*EMB];  // w_proj^T
__device__ __align__(16) bf g_qh[(size_t)MM*C3], g_ql[(size_t)MM*C3];
__device__ __align__(16) bf g_yh[MM*EMB],  g_yl[MM*EMB];

// ------------- helpers -------------
__device__ __forceinline__ void split2(float x, float y, unsigned &hi, unsigned &lo){
    __nv_bfloat16 a=__float2bfloat16(x), b=__float2bfloat16(y);
    hi=(unsigned)__bfloat16_as_ushort(a)|((unsigned)__bfloat16_as_ushort(b)<<16);
    __nv_bfloat16 c=__float2bfloat16(x-__bfloat162float(a));
    __nv_bfloat16 d=__float2bfloat16(y-__bfloat162float(b));
    lo=(unsigned)__bfloat16_as_ushort(c)|((unsigned)__bfloat16_as_ushort(d)<<16);
}
#define MMA(D,A,B) asm volatile("mma.sync.aligned.m16n8k16.row.col.f32.bf16.bf16.f32 " \
  "{%0,%1,%2,%3},{%4,%5,%6,%7},{%8,%9},{%0,%1,%2,%3};" \
  : "+f"(D[0]),"+f"(D[1]),"+f"(D[2]),"+f"(D[3]) \
  : "r"(A[0]),"r"(A[1]),"r"(A[2]),"r"(A[3]),"r"(B[0]),"r"(B[1]))
__device__ __forceinline__ void ldsm4(unsigned a, unsigned r[4]){
    asm volatile("ldmatrix.sync.aligned.m8n8.x4.shared.b16 {%0,%1,%2,%3},[%4];"
      :"=r"(r[0]),"=r"(r[1]),"=r"(r[2]),"=r"(r[3]):"r"(a));
}
__device__ __forceinline__ void ldsm4t(unsigned a, unsigned r[4]){
    asm volatile("ldmatrix.sync.aligned.m8n8.x4.trans.shared.b16 {%0,%1,%2,%3},[%4];"
      :"=r"(r[0]),"=r"(r[1]),"=r"(r[2]),"=r"(r[3]):"r"(a));
}
#define CPA(d,s) asm volatile("cp.async.cg.shared.global [%0],[%1],16;"::"r"(d),"l"(s))
#define CPCOMMIT() asm volatile("cp.async.commit_group;")

// ------------- conversion kernels -------------
__global__ void vsplit(const float* __restrict__ x, bf* hi, bf* lo, int n){
    int i=(blockIdx.x*blockDim.x+threadIdx.x)*2;
    if(i<n){ unsigned h,l; split2(x[i],x[i+1],h,l);
        *(unsigned*)(hi+i)=h; *(unsigned*)(lo+i)=l; }
}
__global__ void tsplit(const float* __restrict__ w, bf* th, bf* tl, int R, int C){
    __shared__ float t[32][33];
    int c0=blockIdx.x*32, r0=blockIdx.y*32, tx=threadIdx.x, ty=threadIdx.y;
    #pragma unroll
    for(int i=0;i<32;i+=8) t[ty+i][tx]=w[(size_t)(r0+ty+i)*C+c0+tx];
    __syncthreads();
    #pragma unroll
    for(int i=0;i<32;i+=8){
        float v=t[tx][ty+i];
        bf hv=__float2bfloat16(v);
        th[(size_t)(c0+ty+i)*R+r0+tx]=hv;
        tl[(size_t)(c0+ty+i)*R+r0+tx]=__float2bfloat16(v-__bfloat162float(hv));
    }
}

// ------------- GEMM: C[M,N]=(Ah+Al)[M,K]@(Bh+Bl)[N,K]^T + bias -------------
// 512 threads, CTA tile 128xBN, 16 warps 4x4, warp tile 32x(BN/4), 3-stage cp.async.
#define SASTR 40
#define ATILE (128*SASTR)
template<int BN,int SPLITOUT>
__global__ __launch_bounds__(512,1) void gemm_mma(
    const bf* __restrict__ Ah, const bf* __restrict__ Al,
    const bf* __restrict__ Bh, const bf* __restrict__ Bl,
    const float* __restrict__ bias,
    float* __restrict__ Cf, bf* __restrict__ Ch, bf* __restrict__ Cl,
    int M, int N, int K)
{
    constexpr int WN   = BN/4;          // warp n-extent (64 or 32)
    constexpr int NF   = WN/8;          // n-fragments per warp (8 or 4)
    constexpr int NH   = WN/32;         // 32-col halves (2 or 1)
    constexpr int BTIL = BN*SASTR;      // B tile elements per half
    constexpr int STG  = (2*ATILE+2*BTIL)*2;   // stage bytes

    extern __shared__ bf sm[];
    const int tid=threadIdx.x, lane=tid&31, w=tid>>5;
    const int wm=(w>>2)*32, wn=(w&3)*WN;
    const int bm=blockIdx.y*128, bn=blockIdx.x*BN;
    unsigned sb0=(unsigned)__cvta_generic_to_shared(sm);
    float acc[2][NF][4];
    #pragma unroll
    for(int a=0;a<2;a++)
      #pragma unroll
      for(int b=0;b<NF;b++){acc[a][b][0]=0;acc[a][b][1]=0;acc[a][b][2]=0;acc[a][b][3]=0;}

    auto loadstage=[&](int st,int k0){
        unsigned base=sb0+st*STG;
        #pragma unroll
        for(int i=0;i<1;i++){           // A: 512 chunks per half (128 rows x 4)
            int r=tid>>2, kc=(tid&3)*8;
            size_t ao=(size_t)(bm+r)*K+k0+kc;
            unsigned so=(r*SASTR+kc)*2;
            CPA(base+so,          Ah+ao);
            CPA(base+ATILE*2+so,  Al+ao);
        }
        #pragma unroll
        for(int i=0;i<BN/128;i++){      // B: BN*4 chunks per half
            int c=tid+i*512, r=c>>2, kc=(c&3)*8;
            size_t bo=(size_t)(bn+r)*K+k0+kc;
            unsigned so=(r*SASTR+kc)*2;
            CPA(base+2*ATILE*2+so,         Bh+bo);
            CPA(base+2*ATILE*2+BTIL*2+so,  Bl+bo);
        }
        CPCOMMIT();
    };

    const int NIT=K/32;
    loadstage(0,0); loadstage(1,32);
    for(int it=0;it<NIT;it++){
        if(it+1<NIT) asm volatile("cp.async.wait_group 1;");
        else         asm volatile("cp.async.wait_group 0;");
        __syncthreads();
        if(it+2<NIT) loadstage((it+2)%3,(it+2)*32);
        unsigned sb=sb0+(it%3)*STG;
        #pragma unroll
        for(int ks=0;ks<2;ks++){
            int kb=ks*16+(lane>>4)*8;
            unsigned ah[2][4], al[2][4];
            #pragma unroll
            for(int mf=0;mf<2;mf++){
                int row=wm+mf*16+(lane&15);
                ldsm4(sb+(row*SASTR+kb)*2, ah[mf]);
                ldsm4(sb+ATILE*2+(row*SASTR+kb)*2, al[mf]);
            }
            #pragma unroll
            for(int nh=0;nh<NH;nh++){
                unsigned bch[4][2], bcl[4][2];
                #pragma unroll
                for(int nb=0;nb<2;nb++){
                    unsigned t[4];
                    int row=wn+nh*32+nb*16+(lane&15);
                    ldsm4(sb+2*ATILE*2+(row*SASTR+kb)*2, t);
                    bch[2*nb][0]=t[0]; bch[2*nb][1]=t[2];
                    bch[2*nb+1][0]=t[1]; bch[2*nb+1][1]=t[3];
                    ldsm4(sb+2*ATILE*2+BTIL*2+(row*SASTR+kb)*2, t);
                    bcl[2*nb][0]=t[0]; bcl[2*nb][1]=t[2];
                    bcl[2*nb+1][0]=t[1]; bcl[2*nb+1][1]=t[3];
                }
                #pragma unroll
                for(int mf=0;mf<2;mf++)
                    #pragma unroll
                    for(int nf=0;nf<4;nf++) MMA(acc[mf][nh*4+nf],ah[mf],bch[nf]);
                #pragma unroll
                for(int mf=0;mf<2;mf++)
                    #pragma unroll
                    for(int nf=0;nf<4;nf++) MMA(acc[mf][nh*4+nf],ah[mf],bcl[nf]);
                #pragma unroll
                for(int mf=0;mf<2;mf++)
                    #pragma unroll
                    for(int nf=0;nf<4;nf++) MMA(acc[mf][nh*4+nf],al[mf],bch[nf]);
            }
        }
    }
    int g=lane>>2, tg=(lane&3)*2;
    #pragma unroll
    for(int mf=0;mf<2;mf++){
        int r0=bm+wm+mf*16+g;
        #pragma unroll
        for(int nf=0;nf<NF;nf++){
            int col=bn+wn+nf*8+tg;
            float b0=bias[col], b1=bias[col+1];
            float v0=acc[mf][nf][0]+b0, v1=acc[mf][nf][1]+b1;
            float v2=acc[mf][nf][2]+b0, v3=acc[mf][nf][3]+b1;
            if(SPLITOUT){
                unsigned hi,lo;
                split2(v0,v1,hi,lo);
                *(unsigned*)(Ch+(size_t)r0*N+col)=hi; *(unsigned*)(Cl+(size_t)r0*N+col)=lo;
                split2(v2,v3,hi,lo);
                *(unsigned*)(Ch+(size_t)(r0+8)*N+col)=hi; *(unsigned*)(Cl+(size_t)(r0+8)*N+col)=lo;
            }else{
                *(float2*)(Cf+(size_t)r0*N+col)=make_float2(v0,v1);
                *(float2*)(Cf+(size_t)(r0+8)*N+col)=make_float2(v2,v3);
            }
        }
    }
}

// ------------- causal flash attention, bf16 split mma, double-buffered K/V ----
#define QSTR 72
#define SKV (4*64*QSTR)
#define KV0 (2*128*QSTR)
__global__ __launch_bounds__(256,1) void attn_mma(
    const bf* __restrict__ qh, const bf* __restrict__ ql,
    bf* __restrict__ yh, bf* __restrict__ yl)
{
    extern __shared__ bf sm[];
    const int tid=threadIdx.x, lane=tid&31, w=tid>>5;
    const int qt=gridDim.x-1-blockIdx.x, qb=qt*128;
    const int bh_=blockIdx.y, b=bh_/HEADS, h=bh_-b*HEADS;
    const size_t rowbase=(size_t)b*TT*C3+h*64;
    unsigned sb=(unsigned)__cvta_generic_to_shared(sm);

    auto loadKV=[&](int st,int kb){
        unsigned base=sb+(KV0+st*SKV)*2;
        #pragma unroll
        for(int i=0;i<2;i++){
            int c=tid+i*256, r=c>>3, kc=(c&7)*8;
            size_t go=rowbase+(size_t)(kb+r)*C3+kc;
            unsigned so=(r*QSTR+kc)*2;
            CPA(base+so,               qh+go+EMB);
            CPA(base+64*QSTR*2+so,     ql+go+EMB);
            CPA(base+2*64*QSTR*2+so,   qh+go+2*EMB);
            CPA(base+3*64*QSTR*2+so,   ql+go+2*EMB);
        }
        CPCOMMIT();
    };

    loadKV(0,0);

    #pragma unroll
    for(int i=0;i<4;i++){
        int c=tid+i*256, r=c>>3, kc=(c&7)*8;
        *(uint4*)(sm+r*QSTR+kc)          =*(const uint4*)(qh+rowbase+(size_t)(qb+r)*C3+kc);
        *(uint4*)(sm+128*QSTR+r*QSTR+kc) =*(const uint4*)(ql+rowbase+(size_t)(qb+r)*C3+kc);
    }
    __syncthreads();
    unsigned qfh[4][4], qfl[4][4];
    {
        int row=w*16+(lane&15);
        #pragma unroll
        for(int ks=0;ks<4;ks++){
            int kb=ks*16+(lane>>4)*8;
            ldsm4(sb+(row*QSTR+kb)*2, qfh[ks]);
            ldsm4(sb+(128*QSTR+row*QSTR+kb)*2, qfl[ks]);
        }
    }
    float m0=-1e30f,m1=-1e30f,l0=0.f,l1=0.f,o[8][4];
    #pragma unroll
    for(int i=0;i<8;i++){o[i][0]=0;o[i][1]=0;o[i][2]=0;o[i][3]=0;}
    const float SC=0.18033688f;
    const int g=lane>>2, tg=(lane&3)*2;
    const int nkt=qb/64+2;

    for(int kt=0;kt<nkt;kt++){
        int kb=kt*64;
        asm volatile("cp.async.wait_group 0;");
        __syncthreads();
        if(kt+1<nkt) loadKV((kt+1)&1,(kt+1)*64);
        unsigned kvb=sb+(KV0+(kt&1)*SKV)*2;
        unsigned KH=kvb, KL=kvb+64*QSTR*2, VH=kvb+2*64*QSTR*2, VL=kvb+3*64*QSTR*2;

        float s[8][4];
        #pragma unroll
        for(int i=0;i<8;i++){s[i][0]=0;s[i][1]=0;s[i][2]=0;s[i][3]=0;}
        #pragma unroll
        for(int ks=0;ks<4;ks++){
            int kbb=ks*16+(lane>>4)*8;
            unsigned kch[8][2], kcl[8][2];
            #pragma unroll
            for(int nb=0;nb<4;nb++){
                unsigned t[4];
                int row=nb*16+(lane&15);
                ldsm4(KH+(row*QSTR+kbb)*2,t);
                kch[2*nb][0]=t[0]; kch[2*nb][1]=t[2];
                kch[2*nb+1][0]=t[1]; kch[2*nb+1][1]=t[3];
                ldsm4(KL+(row*QSTR+kbb)*2,t);
                kcl[2*nb][0]=t[0]; kcl[2*nb][1]=t[2];
                kcl[2*nb+1][0]=t[1]; kcl[2*nb+1][1]=t[3];
            }
            #pragma unroll
            for(int nf=0;nf<8;nf++) MMA(s[nf],qfh[ks],kch[nf]);
            #pragma unroll
            for(int nf=0;nf<8;nf++) MMA(s[nf],qfh[ks],kcl[nf]);
            #pragma unroll
            for(int nf=0;nf<8;nf++) MMA(s[nf],qfl[ks],kch[nf]);
        }
        bool domask=(kb+63 > qb+w*16);
        #pragma unroll
        for(int nf=0;nf<8;nf++)
            #pragma unroll
            for(int r=0;r<4;r++){
                float v=s[nf][r]*SC;
                if(domask){
                    int key=kb+nf*8+tg+(r&1);
                    int qr=qb+w*16+g+((r>>1)<<3);
                    if(key>qr) v=-1e30f;
                }
                s[nf][r]=v;
            }
        float mx0=-1e30f,mx1=-1e30f;
        #pragma unroll
        for(int nf=0;nf<8;nf++){
            mx0=fmaxf(mx0,fmaxf(s[nf][0],s[nf][1]));
            mx1=fmaxf(mx1,fmaxf(s[nf][2],s[nf][3]));
        }
        mx0=fmaxf(mx0,__shfl_xor_sync(0xffffffffu,mx0,1));
        mx0=fmaxf(mx0,__shfl_xor_sync(0xffffffffu,mx0,2));
        mx1=fmaxf(mx1,__shfl_xor_sync(0xffffffffu,mx1,1));
        mx1=fmaxf(mx1,__shfl_xor_sync(0xffffffffu,mx1,2));
        float nm0=fmaxf(m0,mx0), nm1=fmaxf(m1,mx1);
        float a0=exp2f(m0-nm0), a1=exp2f(m1-nm1);
        m0=nm0; m1=nm1;
        float rs0=0.f, rs1=0.f;
        #pragma unroll
        for(int nf=0;nf<8;nf++){
            s[nf][0]=exp2f(s[nf][0]-nm0); s[nf][1]=exp2f(s[nf][1]-nm0);
            s[nf][2]=exp2f(s[nf][2]-nm1); s[nf][3]=exp2f(s[nf][3]-nm1);
            rs0+=s[nf][0]+s[nf][1]; rs1+=s[nf][2]+s[nf][3];
        }
        rs0+=__shfl_xor_sync(0xffffffffu,rs0,1); rs0+=__shfl_xor_sync(0xffffffffu,rs0,2);
        rs1+=__shfl_xor_sync(0xffffffffu,rs1,1); rs1+=__shfl_xor_sync(0xffffffffu,rs1,2);
        l0=l0*a0+rs0; l1=l1*a1+rs1;
        #pragma unroll
        for(int i=0;i<8;i++){o[i][0]*=a0;o[i][1]*=a0;o[i][2]*=a1;o[i][3]*=a1;}
        #pragma unroll
        for(int ks=0;ks<4;ks++){
            unsigned ph[4],pl[4];
            split2(s[2*ks][0],s[2*ks][1],ph[0],pl[0]);
            split2(s[2*ks][2],s[2*ks][3],ph[1],pl[1]);
            split2(s[2*ks+1][0],s[2*ks+1][1],ph[2],pl[2]);
            split2(s[2*ks+1][2],s[2*ks+1][3],ph[3],pl[3]);
            int row=ks*16+(lane&15);
            unsigned vch[8][2], vcl[8][2];
            #pragma unroll
            for(int db=0;db<4;db++){
                unsigned t[4];
                int dbb=db*16+(lane>>4)*8;
                ldsm4t(VH+(row*QSTR+dbb)*2,t);
                vch[2*db][0]=t[0]; vch[2*db][1]=t[1];
                vch[2*db+1][0]=t[2]; vch[2*db+1][1]=t[3];
                ldsm4t(VL+(row*QSTR+dbb)*2,t);
                vcl[2*db][0]=t[0]; vcl[2*db][1]=t[1];
                vcl[2*db+1][0]=t[2]; vcl[2*db+1][1]=t[3];
            }
            #pragma unroll
            for(int nf=0;nf<8;nf++) MMA(o[nf],ph,vch[nf]);
            #pragma unroll
            for(int nf=0;nf<8;nf++) MMA(o[nf],ph,vcl[nf]);
            #pragma unroll
            for(int nf=0;nf<8;nf++) MMA(o[nf],pl,vch[nf]);
        }
    }
    float i0=1.f/l0, i1=1.f/l1;
    #pragma unroll
    for(int dn=0;dn<8;dn++){
        int col=h*64+dn*8+tg;
        size_t r0=(size_t)b*TT+qb+w*16+g;
        unsigned hi,lo;
        split2(o[dn][0]*i0,o[dn][1]*i0,hi,lo);
        *(unsigned*)(yh+r0*EMB+col)=hi; *(unsigned*)(yl+r0*EMB+col)=lo;
        split2(o[dn][2]*i1,o[dn][3]*i1,hi,lo);
        *(unsigned*)(yh+(r0+8)*EMB+col)=hi; *(unsigned*)(yl+(r0+8)*EMB+col)=lo;
    }
}

// ------------- launch -------------
extern "C" void kernel_launch(void* const* d_in, const int* in_sizes, int n_in,
                              void* d_out, int out_size)
{
    const float* x=(const float*)d_in[0];
    const float* w_qkv=(const float*)d_in[1];
    const float* b_qkv=(const float*)d_in[2];
    const float* w_proj=(const float*)d_in[3];
    const float* b_proj=(const float*)d_in[4];
    float* out=(float*)d_out;

    void *xh,*xl,*wqh,*wql,*wph,*wpl,*qhp,*qlp,*yhp,*ylp;
    cudaGetSymbolAddress(&xh,g_xh);   cudaGetSymbolAddress(&xl,g_xl);
    cudaGetSymbolAddress(&wqh,g_wqh); cudaGetSymbolAddress(&wql,g_wql);
    cudaGetSymbolAddress(&wph,g_wph); cudaGetSymbolAddress(&wpl,g_wpl);
    cudaGetSymbolAddress(&qhp,g_qh);  cudaGetSymbolAddress(&qlp,g_ql);
    cudaGetSymbolAddress(&yhp,g_yh);  cudaGetSymbolAddress(&ylp,g_yl);

    const int GSM1=3*(2*ATILE+2*256*SASTR)*2;     // 184320 B (BN=256)
    const int GSM2=3*(2*ATILE+2*128*SASTR)*2;     // 122880 B (BN=128)
    const int ASM=(2*128*QSTR+2*SKV)*2;           // 110592 B
    cudaFuncSetAttribute((gemm_mma<256,1>),cudaFuncAttributeMaxDynamicSharedMemorySize,GSM1);
    cudaFuncSetAttribute((gemm_mma<128,0>),cudaFuncAttributeMaxDynamicSharedMemorySize,GSM2);
    cudaFuncSetAttribute(attn_mma,cudaFuncAttributeMaxDynamicSharedMemorySize,ASM);

    vsplit<<<(MM*EMB/2+255)/256,256>>>(x,(bf*)xh,(bf*)xl,MM*EMB);
    tsplit<<<dim3(C3/32,EMB/32),dim3(32,8)>>>(w_qkv,(bf*)wqh,(bf*)wql,EMB,C3);
    tsplit<<<dim3(EMB/32,EMB/32),dim3(32,8)>>>(w_proj,(bf*)wph,(bf*)wpl,EMB,EMB);

    gemm_mma<256,1><<<dim3(C3/256,MM/128),512,GSM1>>>(
        (const bf*)xh,(const bf*)xl,(const bf*)wqh,(const bf*)wql,b_qkv,
        nullptr,(bf*)qhp,(bf*)qlp, MM,C3,EMB);

    attn_mma<<<dim3(TT/128,BB*HEADS),256,ASM>>>(
        (const bf*)qhp,(const bf*)qlp,(bf*)yhp,(bf*)ylp);

    gemm_mma<128,0><<<dim3(EMB/128,MM/128),512,GSM2>>>(
        (const bf*)yhp,(const bf*)ylp,(const bf*)wph,(const bf*)wpl,b_proj,
        out,nullptr,nullptr, MM,EMB,EMB);
}